// round 1
// baseline (speedup 1.0000x reference)
#include <cuda_runtime.h>
#include <math.h>

// ---------------------------------------------------------------------------
// EncoderBlock: B=16, N=1024, DIM=768, HEADS=12, HEAD_DIM=64, HIDDEN=3072
// T = B*N = 16384 tokens.
// Pipeline:
//   xn1 = LN1(x)
//   qkv = xn1 @ qkv_w + qkv_b                 [T, 2304]
//   ctx = attention(qkv)                      [T, 768]
//   x2  = x + (ctx @ proj_w + proj_b)
//   ffin = LN2(x2)
//   hid = gelu(ffin @ fc1_w + fc1_b)          [T, 3072]
//   x3  = ffin + (hid @ fc2_w + fc2_b)        (residual from NORMALIZED tensor!)
//   out = LN3(x3)
// ---------------------------------------------------------------------------

#define T_TOK 16384

// Scratch (device globals: allocation-guard safe)
__device__ float g_xn1 [T_TOK * 768];
__device__ float g_qkv [T_TOK * 2304];
__device__ float g_ctx [T_TOK * 768];
__device__ float g_x2  [T_TOK * 768];
__device__ float g_ffin[T_TOK * 768];
__device__ float g_hid [T_TOK * 3072];
__device__ float g_x3  [T_TOK * 768];

// ---------------------------------------------------------------------------
// LayerNorm over last dim = 768. One block per row, 256 threads, 3 elems/thread.
// ---------------------------------------------------------------------------
__global__ __launch_bounds__(256) void ln_kernel(
    const float* __restrict__ in, const float* __restrict__ g,
    const float* __restrict__ b, float* __restrict__ out)
{
    int row = blockIdx.x;
    const float* p = in + (size_t)row * 768;
    float v[3];
    float s = 0.f, ss = 0.f;
#pragma unroll
    for (int i = 0; i < 3; i++) {
        v[i] = p[threadIdx.x + i * 256];
        s += v[i];
        ss += v[i] * v[i];
    }
#pragma unroll
    for (int o = 16; o > 0; o >>= 1) {
        s  += __shfl_xor_sync(0xffffffffu, s,  o);
        ss += __shfl_xor_sync(0xffffffffu, ss, o);
    }
    __shared__ float rs[8], rss[8];
    int w = threadIdx.x >> 5, lane = threadIdx.x & 31;
    if (lane == 0) { rs[w] = s; rss[w] = ss; }
    __syncthreads();
    s = 0.f; ss = 0.f;
#pragma unroll
    for (int i = 0; i < 8; i++) { s += rs[i]; ss += rss[i]; }
    float mean = s * (1.0f / 768.0f);
    float var  = ss * (1.0f / 768.0f) - mean * mean;
    float rstd = rsqrtf(var + 1e-5f);
    float* q = out + (size_t)row * 768;
#pragma unroll
    for (int i = 0; i < 3; i++) {
        int c = threadIdx.x + i * 256;
        q[c] = (v[i] - mean) * rstd * g[c] + b[c];
    }
}

// ---------------------------------------------------------------------------
// SGEMM: C[M,N] = A[M,K] @ B[K,N] + bias[N], with epilogue:
//   EPI=0: none, EPI=1: exact GELU, EPI=2: += res[M,N]
// 128x128 block tile, K-tile 8, 256 threads, 8x8 per thread.
// Requires M%128==0, N%128==0, K%8==0 (true for all calls here).
// ---------------------------------------------------------------------------
template <int EPI>
__global__ __launch_bounds__(256) void sgemm_kernel(
    const float* __restrict__ A, const float* __restrict__ B,
    const float* __restrict__ bias, const float* __restrict__ res,
    float* __restrict__ C, int M, int N, int K)
{
    __shared__ float As[8][128];
    __shared__ float Bs[8][128];

    int tid = threadIdx.x;
    int tx = tid & 15, ty = tid >> 4;
    int bm = blockIdx.y * 128, bn = blockIdx.x * 128;

    int arow = tid >> 1, acol = (tid & 1) * 4;
    int brow = tid >> 5, bcol = (tid & 31) * 4;

    const float* Aptr = A + (size_t)(bm + arow) * K + acol;
    const float* Bptr = B + (size_t)brow * N + bn + bcol;

    float acc[8][8];
#pragma unroll
    for (int i = 0; i < 8; i++)
#pragma unroll
        for (int j = 0; j < 8; j++) acc[i][j] = 0.f;

    for (int k0 = 0; k0 < K; k0 += 8) {
        float4 a4 = *(const float4*)(Aptr + k0);
        float4 b4 = *(const float4*)(Bptr + (size_t)k0 * N);
        As[acol + 0][arow] = a4.x;
        As[acol + 1][arow] = a4.y;
        As[acol + 2][arow] = a4.z;
        As[acol + 3][arow] = a4.w;
        *(float4*)&Bs[brow][bcol] = b4;
        __syncthreads();
#pragma unroll
        for (int kk = 0; kk < 8; kk++) {
            float4 a0 = *(const float4*)&As[kk][ty * 8];
            float4 a1 = *(const float4*)&As[kk][ty * 8 + 4];
            float4 b0 = *(const float4*)&Bs[kk][tx * 8];
            float4 b1 = *(const float4*)&Bs[kk][tx * 8 + 4];
            float ar[8] = {a0.x, a0.y, a0.z, a0.w, a1.x, a1.y, a1.z, a1.w};
            float br[8] = {b0.x, b0.y, b0.z, b0.w, b1.x, b1.y, b1.z, b1.w};
#pragma unroll
            for (int i = 0; i < 8; i++)
#pragma unroll
                for (int j = 0; j < 8; j++)
                    acc[i][j] += ar[i] * br[j];
        }
        __syncthreads();
    }

#pragma unroll
    for (int i = 0; i < 8; i++) {
        int row = bm + ty * 8 + i;
#pragma unroll
        for (int j = 0; j < 8; j++) {
            int col = bn + tx * 8 + j;
            float v = acc[i][j] + bias[col];
            if (EPI == 1) v = 0.5f * v * (1.0f + erff(v * 0.70710678118654752f));
            if (EPI == 2) v += res[(size_t)row * N + col];
            C[(size_t)row * N + col] = v;
        }
    }
}

// ---------------------------------------------------------------------------
// Flash-style attention. qkv layout: [T, 3, 12, 64] (Q at +0, K at +768, V at +1536)
// Grid: (N/64, B*H) = (16, 192). Block: 256 threads.
// Br=64 queries per block, Bc=32 keys per tile, 32 tiles.
// Thread mapping: row = tid/4 (0..63), quad = tid%4.
//   S compute: thread owns 8 key columns (quad*8..+7)
//   O accum:   thread owns 16 head dims   (quad*16..+15)
// ---------------------------------------------------------------------------
__global__ __launch_bounds__(256) void attn_kernel(
    const float* __restrict__ qkv, float* __restrict__ ctx)
{
    __shared__ float Qs[64 * 65];
    __shared__ float Ks[32 * 65];
    __shared__ float Vs[32 * 65];
    __shared__ float Ps[64 * 33];

    int tid = threadIdx.x;
    int row = tid >> 2, quad = tid & 3;
    int bh = blockIdx.y;
    int b = bh / 12, h = bh % 12;
    int t0 = b * 1024;
    int q0 = blockIdx.x * 64;

    // Load Q tile [64, 64]
    for (int i = tid; i < 1024; i += 256) {
        int r = i >> 4, c = (i & 15) * 4;
        float4 v = *(const float4*)(qkv + (size_t)(t0 + q0 + r) * 2304 + h * 64 + c);
        Qs[r * 65 + c + 0] = v.x;
        Qs[r * 65 + c + 1] = v.y;
        Qs[r * 65 + c + 2] = v.z;
        Qs[r * 65 + c + 3] = v.w;
    }
    __syncthreads();

    float m = -1e30f, l = 0.f;
    float o[16];
#pragma unroll
    for (int i = 0; i < 16; i++) o[i] = 0.f;

    for (int kt = 0; kt < 32; kt++) {
        int kbase = kt * 32;
        // Load K, V tiles [32, 64]
        for (int i = tid; i < 512; i += 256) {
            int r = i >> 4, c = (i & 15) * 4;
            const float* kp = qkv + (size_t)(t0 + kbase + r) * 2304 + 768 + h * 64 + c;
            float4 kv = *(const float4*)kp;
            float4 vv = *(const float4*)(kp + 768);
            Ks[r * 65 + c + 0] = kv.x; Ks[r * 65 + c + 1] = kv.y;
            Ks[r * 65 + c + 2] = kv.z; Ks[r * 65 + c + 3] = kv.w;
            Vs[r * 65 + c + 0] = vv.x; Vs[r * 65 + c + 1] = vv.y;
            Vs[r * 65 + c + 2] = vv.z; Vs[r * 65 + c + 3] = vv.w;
        }
        __syncthreads();

        // S = Q K^T * scale  (each thread: 8 key cols)
        float s[8];
#pragma unroll
        for (int jj = 0; jj < 8; jj++) {
            int j = quad * 8 + jj;
            float acc = 0.f;
#pragma unroll
            for (int d = 0; d < 64; d++)
                acc += Qs[row * 65 + d] * Ks[j * 65 + d];
            s[jj] = acc * 0.125f;
        }

        // Online softmax
        float tmax = s[0];
#pragma unroll
        for (int jj = 1; jj < 8; jj++) tmax = fmaxf(tmax, s[jj]);
        tmax = fmaxf(tmax, __shfl_xor_sync(0xffffffffu, tmax, 1));
        tmax = fmaxf(tmax, __shfl_xor_sync(0xffffffffu, tmax, 2));
        float mn = fmaxf(m, tmax);
        float alpha = __expf(m - mn);
        float psum = 0.f;
#pragma unroll
        for (int jj = 0; jj < 8; jj++) {
            float p = __expf(s[jj] - mn);
            Ps[row * 33 + quad * 8 + jj] = p;
            psum += p;
        }
        psum += __shfl_xor_sync(0xffffffffu, psum, 1);
        psum += __shfl_xor_sync(0xffffffffu, psum, 2);
        l = l * alpha + psum;
        m = mn;
#pragma unroll
        for (int i = 0; i < 16; i++) o[i] *= alpha;
        __syncthreads();

        // O += P @ V  (each thread: 16 head dims)
#pragma unroll
        for (int dd = 0; dd < 16; dd++) {
            int d = quad * 16 + dd;
            float acc = 0.f;
#pragma unroll
            for (int j = 0; j < 32; j++)
                acc += Ps[row * 33 + j] * Vs[j * 65 + d];
            o[dd] += acc;
        }
        __syncthreads();
    }

    float inv = 1.0f / l;
    float* op = ctx + (size_t)(t0 + q0 + row) * 768 + h * 64 + quad * 16;
#pragma unroll
    for (int dd = 0; dd < 16; dd++) op[dd] = o[dd] * inv;
}

// ---------------------------------------------------------------------------
// Host launch (graph-capturable: kernel launches + symbol lookups only)
// ---------------------------------------------------------------------------
extern "C" void kernel_launch(void* const* d_in, const int* in_sizes, int n_in,
                              void* d_out, int out_size)
{
    const float* x      = (const float*)d_in[0];
    const float* ln1_g  = (const float*)d_in[1];
    const float* ln1_b  = (const float*)d_in[2];
    const float* qkv_w  = (const float*)d_in[3];
    const float* qkv_b  = (const float*)d_in[4];
    const float* proj_w = (const float*)d_in[5];
    const float* proj_b = (const float*)d_in[6];
    const float* ln2_g  = (const float*)d_in[7];
    const float* ln2_b  = (const float*)d_in[8];
    const float* fc1_w  = (const float*)d_in[9];
    const float* fc1_b  = (const float*)d_in[10];
    const float* fc2_w  = (const float*)d_in[11];
    const float* fc2_b  = (const float*)d_in[12];
    const float* ln3_g  = (const float*)d_in[13];
    const float* ln3_b  = (const float*)d_in[14];
    float* out = (float*)d_out;

    float *xn1, *qkv, *ctx, *x2, *ffin, *hid, *x3;
    cudaGetSymbolAddress((void**)&xn1,  g_xn1);
    cudaGetSymbolAddress((void**)&qkv,  g_qkv);
    cudaGetSymbolAddress((void**)&ctx,  g_ctx);
    cudaGetSymbolAddress((void**)&x2,   g_x2);
    cudaGetSymbolAddress((void**)&ffin, g_ffin);
    cudaGetSymbolAddress((void**)&hid,  g_hid);
    cudaGetSymbolAddress((void**)&x3,   g_x3);

    const int T = T_TOK;

    // 1) xn1 = LN1(x)
    ln_kernel<<<T, 256>>>(x, ln1_g, ln1_b, xn1);
    // 2) qkv = xn1 @ qkv_w + qkv_b
    sgemm_kernel<0><<<dim3(2304 / 128, T / 128), 256>>>(xn1, qkv_w, qkv_b, nullptr, qkv, T, 2304, 768);
    // 3) ctx = attention(qkv)
    attn_kernel<<<dim3(16, 192), 256>>>(qkv, ctx);
    // 4) x2 = x + ctx @ proj_w + proj_b
    sgemm_kernel<2><<<dim3(768 / 128, T / 128), 256>>>(ctx, proj_w, proj_b, x, x2, T, 768, 768);
    // 5) ffin = LN2(x2)
    ln_kernel<<<T, 256>>>(x2, ln2_g, ln2_b, ffin);
    // 6) hid = gelu(ffin @ fc1_w + fc1_b)
    sgemm_kernel<1><<<dim3(3072 / 128, T / 128), 256>>>(ffin, fc1_w, fc1_b, nullptr, hid, T, 3072, 768);
    // 7) x3 = ffin + hid @ fc2_w + fc2_b   (residual from NORMALIZED tensor)
    sgemm_kernel<2><<<dim3(768 / 128, T / 128), 256>>>(hid, fc2_w, fc2_b, ffin, x3, T, 768, 3072);
    // 8) out = LN3(x3)
    ln_kernel<<<T, 256>>>(x3, ln3_g, ln3_b, out);
}

// round 2
// speedup vs baseline: 4.2516x; 4.2516x over previous
#include <cuda_runtime.h>
#include <math.h>

// ---------------------------------------------------------------------------
// EncoderBlock: B=16, N=1024, DIM=768, HEADS=12, HEAD_DIM=64, HIDDEN=3072
// T = 16384 tokens. All matmuls on tensor pipe via mma.sync tf32.
// ---------------------------------------------------------------------------

#define T_TOK 16384

// Scratch (device globals: allocation-guard safe)
__device__ float g_xn1 [T_TOK * 768];
__device__ float g_qkv [T_TOK * 2304];
__device__ float g_ctx [T_TOK * 768];
__device__ float g_x2  [T_TOK * 768];
__device__ float g_ffin[T_TOK * 768];
__device__ float g_hid [T_TOK * 3072];
__device__ float g_x3  [T_TOK * 768];
// tf32-rounded weights
__device__ float g_wq  [768 * 2304];
__device__ float g_wp  [768 * 768];
__device__ float g_w1  [768 * 3072];
__device__ float g_w2  [3072 * 768];

// ---------------------------------------------------------------------------
// helpers
// ---------------------------------------------------------------------------
__device__ __forceinline__ unsigned f2u(float x) { return __float_as_uint(x); }

__device__ __forceinline__ float to_tf32(float x) {
    unsigned u;
    asm("cvt.rna.tf32.f32 %0, %1;" : "=r"(u) : "f"(x));
    return __uint_as_float(u);
}

__device__ __forceinline__ void mma8(float* c, const unsigned* a, const unsigned* b) {
    asm volatile(
        "mma.sync.aligned.m16n8k8.row.col.f32.tf32.tf32.f32 "
        "{%0,%1,%2,%3}, {%4,%5,%6,%7}, {%8,%9}, {%0,%1,%2,%3};\n"
        : "+f"(c[0]), "+f"(c[1]), "+f"(c[2]), "+f"(c[3])
        : "r"(a[0]), "r"(a[1]), "r"(a[2]), "r"(a[3]), "r"(b[0]), "r"(b[1]));
}

__device__ __forceinline__ void cp16(float* dst, const float* src) {
    unsigned d = (unsigned)__cvta_generic_to_shared(dst);
    asm volatile("cp.async.cg.shared.global [%0], [%1], 16;\n" :: "r"(d), "l"(src));
}
__device__ __forceinline__ void cp_commit() { asm volatile("cp.async.commit_group;\n"); }
template <int N>
__device__ __forceinline__ void cp_wait() { asm volatile("cp.async.wait_group %0;\n" :: "n"(N)); }

// ---------------------------------------------------------------------------
// weight pre-round to tf32 (rna)
// ---------------------------------------------------------------------------
__global__ __launch_bounds__(256) void round4_kernel(const float* __restrict__ in,
                                                     float* __restrict__ out, int n4)
{
    int i = blockIdx.x * 256 + threadIdx.x;
    if (i < n4) {
        float4 v = ((const float4*)in)[i];
        v.x = to_tf32(v.x); v.y = to_tf32(v.y); v.z = to_tf32(v.z); v.w = to_tf32(v.w);
        ((float4*)out)[i] = v;
    }
}

// ---------------------------------------------------------------------------
// LayerNorm over 768. ROUND: round output to tf32 (feeds a GEMM A operand).
// ---------------------------------------------------------------------------
template <bool ROUND>
__global__ __launch_bounds__(256) void ln_kernel(
    const float* __restrict__ in, const float* __restrict__ g,
    const float* __restrict__ b, float* __restrict__ out)
{
    int row = blockIdx.x;
    const float* p = in + (size_t)row * 768;
    float v[3];
    float s = 0.f, ss = 0.f;
#pragma unroll
    for (int i = 0; i < 3; i++) {
        v[i] = p[threadIdx.x + i * 256];
        s += v[i]; ss += v[i] * v[i];
    }
#pragma unroll
    for (int o = 16; o > 0; o >>= 1) {
        s  += __shfl_xor_sync(0xffffffffu, s,  o);
        ss += __shfl_xor_sync(0xffffffffu, ss, o);
    }
    __shared__ float rs[8], rss[8];
    int w = threadIdx.x >> 5, lane = threadIdx.x & 31;
    if (lane == 0) { rs[w] = s; rss[w] = ss; }
    __syncthreads();
    s = 0.f; ss = 0.f;
#pragma unroll
    for (int i = 0; i < 8; i++) { s += rs[i]; ss += rss[i]; }
    float mean = s * (1.0f / 768.0f);
    float var  = ss * (1.0f / 768.0f) - mean * mean;
    float rstd = rsqrtf(var + 1e-5f);
    float* q = out + (size_t)row * 768;
#pragma unroll
    for (int i = 0; i < 3; i++) {
        int c = threadIdx.x + i * 256;
        float r = (v[i] - mean) * rstd * g[c] + b[c];
        q[c] = ROUND ? to_tf32(r) : r;
    }
}

// ---------------------------------------------------------------------------
// tf32 mma GEMM: C[M,N] = A[M,K] @ B[K,N] + bias, epilogue:
//   EPI=0: none; EPI=1: exact GELU then tf32-round; EPI=2: += res
// 128x128x32 tiles, 256 threads (8 warps, 2x4), warp tile 64x32.
// ---------------------------------------------------------------------------
#define GA_S 36
#define GB_S 140
#define GA_BUF (128 * GA_S)
#define GB_BUF (32 * GB_S)
#define GEMM_SMEM ((2 * GA_BUF + 2 * GB_BUF) * 4)

template <int EPI>
__global__ __launch_bounds__(256) void gemm_tf32(
    const float* __restrict__ A, const float* __restrict__ B,
    const float* __restrict__ bias, const float* __restrict__ res,
    float* __restrict__ C, int M, int N, int K)
{
    extern __shared__ float smx[];
    float* As = smx;                // [2][128][GA_S]
    float* Bs = smx + 2 * GA_BUF;   // [2][32][GB_S]

    int tid = threadIdx.x;
    int warp = tid >> 5, lane = tid & 31;
    int g = lane >> 2, t = lane & 3;
    int wm = (warp & 1) * 64, wn = (warp >> 1) * 32;
    int bm = blockIdx.y * 128, bn = blockIdx.x * 128;

    int ar = tid >> 3, ac = (tid & 7) * 4;   // A copy map
    int br = tid >> 5, bc = (tid & 31) * 4;  // B copy map

    float acc[4][4][4];
#pragma unroll
    for (int i = 0; i < 4; i++)
#pragma unroll
        for (int j = 0; j < 4; j++)
#pragma unroll
            for (int q = 0; q < 4; q++) acc[i][j][q] = 0.f;

    const float* Agb = A + (size_t)bm * K;
    const float* Bgb = B + bn;

    // prologue: tile 0
    {
#pragma unroll
        for (int i = 0; i < 4; i++) {
            int r = ar + 32 * i;
            cp16(&As[r * GA_S + ac], Agb + (size_t)r * K + ac);
        }
#pragma unroll
        for (int i = 0; i < 4; i++) {
            int r = br + 8 * i;
            cp16(&Bs[r * GB_S + bc], Bgb + (size_t)r * N + bc);
        }
        cp_commit();
    }

    int ntile = K >> 5;
    for (int tt = 0; tt < ntile; tt++) {
        if (tt + 1 < ntile) {
            int buf = (tt + 1) & 1;
            int k0 = (tt + 1) * 32;
#pragma unroll
            for (int i = 0; i < 4; i++) {
                int r = ar + 32 * i;
                cp16(&As[buf * GA_BUF + r * GA_S + ac], Agb + (size_t)r * K + k0 + ac);
            }
#pragma unroll
            for (int i = 0; i < 4; i++) {
                int r = br + 8 * i;
                cp16(&Bs[buf * GB_BUF + r * GB_S + bc], Bgb + (size_t)(k0 + r) * N + bc);
            }
            cp_commit();
            cp_wait<1>();
        } else {
            cp_wait<0>();
        }
        __syncthreads();

        int buf = tt & 1;
#pragma unroll
        for (int s = 0; s < 4; s++) {
            unsigned a[4][4], b[4][2];
            const float* Ab = &As[buf * GA_BUF + (wm + g) * GA_S + 8 * s + t];
#pragma unroll
            for (int mt = 0; mt < 4; mt++) {
                const float* p = Ab + mt * 16 * GA_S;
                a[mt][0] = f2u(p[0]);
                a[mt][1] = f2u(p[8 * GA_S]);
                a[mt][2] = f2u(p[4]);
                a[mt][3] = f2u(p[8 * GA_S + 4]);
            }
            const float* Bb = &Bs[buf * GB_BUF + (8 * s + t) * GB_S + wn + g];
#pragma unroll
            for (int nt = 0; nt < 4; nt++) {
                const float* p = Bb + nt * 8;
                b[nt][0] = f2u(p[0]);
                b[nt][1] = f2u(p[4 * GB_S]);
            }
#pragma unroll
            for (int mt = 0; mt < 4; mt++)
#pragma unroll
                for (int nt = 0; nt < 4; nt++)
                    mma8(acc[mt][nt], a[mt], b[nt]);
        }
        __syncthreads();
    }

    // epilogue
#pragma unroll
    for (int mt = 0; mt < 4; mt++) {
        int r0 = bm + wm + mt * 16 + g;
        int r1 = r0 + 8;
#pragma unroll
        for (int nt = 0; nt < 4; nt++) {
            int col = bn + wn + nt * 8 + 2 * t;
            float b0 = bias[col], b1 = bias[col + 1];
            float v0 = acc[mt][nt][0] + b0, v1 = acc[mt][nt][1] + b1;
            float v2 = acc[mt][nt][2] + b0, v3 = acc[mt][nt][3] + b1;
            if (EPI == 1) {
                v0 = to_tf32(0.5f * v0 * (1.0f + erff(v0 * 0.70710678118654752f)));
                v1 = to_tf32(0.5f * v1 * (1.0f + erff(v1 * 0.70710678118654752f)));
                v2 = to_tf32(0.5f * v2 * (1.0f + erff(v2 * 0.70710678118654752f)));
                v3 = to_tf32(0.5f * v3 * (1.0f + erff(v3 * 0.70710678118654752f)));
            }
            if (EPI == 2) {
                float2 ra = *(const float2*)(res + (size_t)r0 * N + col);
                float2 rb = *(const float2*)(res + (size_t)r1 * N + col);
                v0 += ra.x; v1 += ra.y; v2 += rb.x; v3 += rb.y;
            }
            *(float2*)(C + (size_t)r0 * N + col) = make_float2(v0, v1);
            *(float2*)(C + (size_t)r1 * N + col) = make_float2(v2, v3);
        }
    }
}

// ---------------------------------------------------------------------------
// Flash attention with tf32 mma. Br=64, Bc=64, 128 threads (4 warps).
// Each warp: 16 q-rows. Q frags in regs for whole kernel; P via smem.
// qkv layout [T, 2304]: Q +0, K +768, V +1536 (per head h: +h*64).
// ---------------------------------------------------------------------------
#define AT_S 76
#define ATT_SMEM (3 * 64 * AT_S * 4)

__global__ __launch_bounds__(128) void attn_tf32(
    const float* __restrict__ qkv, float* __restrict__ ctx)
{
    extern __shared__ float smx[];
    float* QPs = smx;                 // 64 x AT_S : Q then reused as P
    float* Ks  = smx + 64 * AT_S;
    float* Vs  = smx + 2 * 64 * AT_S;

    int tid = threadIdx.x, warp = tid >> 5, lane = tid & 31;
    int g = lane >> 2, t = lane & 3;
    int bh = blockIdx.y, b = bh / 12, h = bh % 12;
    size_t base = (size_t)b * 1024 * 2304 + h * 64;
    int q0 = blockIdx.x * 64;

    // load Q (pre-scaled by 1/8)
#pragma unroll
    for (int i = 0; i < 8; i++) {
        int idx = tid + i * 128;
        int r = idx >> 4, c = (idx & 15) * 4;
        float4 v = *(const float4*)(qkv + base + (size_t)(q0 + r) * 2304 + c);
        v.x *= 0.125f; v.y *= 0.125f; v.z *= 0.125f; v.w *= 0.125f;
        *(float4*)&QPs[r * AT_S + c] = v;
    }
    __syncthreads();

    // extract Q fragments (held in regs the whole kernel)
    unsigned qa[8][4];
    {
        const float* p0 = &QPs[(warp * 16 + g) * AT_S + t];
#pragma unroll
        for (int s = 0; s < 8; s++) {
            qa[s][0] = f2u(p0[8 * s]);
            qa[s][1] = f2u(p0[8 * AT_S + 8 * s]);
            qa[s][2] = f2u(p0[8 * s + 4]);
            qa[s][3] = f2u(p0[8 * AT_S + 8 * s + 4]);
        }
    }
    __syncthreads();   // QPs now free -> P buffer

    float* PsW = QPs + warp * 16 * AT_S;

    float o[8][4];
#pragma unroll
    for (int i = 0; i < 8; i++)
#pragma unroll
        for (int j = 0; j < 4; j++) o[i][j] = 0.f;
    float m0 = -1e30f, m1 = -1e30f, l0 = 0.f, l1 = 0.f;

    for (int kt = 0; kt < 16; kt++) {
        // load K, V tiles [64, 64]
#pragma unroll
        for (int i = 0; i < 8; i++) {
            int idx = tid + i * 128;
            int r = idx >> 4, c = (idx & 15) * 4;
            const float* kp = qkv + base + (size_t)(kt * 64 + r) * 2304 + 768 + c;
            *(float4*)&Ks[r * AT_S + c] = *(const float4*)kp;
            *(float4*)&Vs[r * AT_S + c] = *(const float4*)(kp + 768);
        }
        __syncthreads();

        // S = Q K^T (scaled already)
        float sc[8][4];
#pragma unroll
        for (int i = 0; i < 8; i++)
#pragma unroll
            for (int j = 0; j < 4; j++) sc[i][j] = 0.f;
#pragma unroll
        for (int s = 0; s < 8; s++) {
            const float* Kb = &Ks[g * AT_S + 8 * s + t];
#pragma unroll
            for (int nt = 0; nt < 8; nt++) {
                unsigned bb[2];
                const float* p = Kb + nt * 8 * AT_S;
                bb[0] = f2u(p[0]);
                bb[1] = f2u(p[4]);
                mma8(sc[nt], qa[s], bb);
            }
        }

        // online softmax (rows g and g+8 of this warp's 16-row strip)
        float mx0 = -1e30f, mx1 = -1e30f;
#pragma unroll
        for (int nt = 0; nt < 8; nt++) {
            mx0 = fmaxf(mx0, fmaxf(sc[nt][0], sc[nt][1]));
            mx1 = fmaxf(mx1, fmaxf(sc[nt][2], sc[nt][3]));
        }
        mx0 = fmaxf(mx0, __shfl_xor_sync(0xffffffffu, mx0, 1));
        mx0 = fmaxf(mx0, __shfl_xor_sync(0xffffffffu, mx0, 2));
        mx1 = fmaxf(mx1, __shfl_xor_sync(0xffffffffu, mx1, 1));
        mx1 = fmaxf(mx1, __shfl_xor_sync(0xffffffffu, mx1, 2));
        float nm0 = fmaxf(m0, mx0), nm1 = fmaxf(m1, mx1);
        float al0 = __expf(m0 - nm0), al1 = __expf(m1 - nm1);
        float ps0 = 0.f, ps1 = 0.f;
#pragma unroll
        for (int nt = 0; nt < 8; nt++) {
            float p0 = __expf(sc[nt][0] - nm0);
            float p1 = __expf(sc[nt][1] - nm0);
            float p2 = __expf(sc[nt][2] - nm1);
            float p3 = __expf(sc[nt][3] - nm1);
            ps0 += p0 + p1; ps1 += p2 + p3;
            *(float2*)&PsW[g * AT_S + nt * 8 + 2 * t]       = make_float2(p0, p1);
            *(float2*)&PsW[(g + 8) * AT_S + nt * 8 + 2 * t] = make_float2(p2, p3);
        }
        ps0 += __shfl_xor_sync(0xffffffffu, ps0, 1);
        ps0 += __shfl_xor_sync(0xffffffffu, ps0, 2);
        ps1 += __shfl_xor_sync(0xffffffffu, ps1, 1);
        ps1 += __shfl_xor_sync(0xffffffffu, ps1, 2);
        l0 = l0 * al0 + ps0;
        l1 = l1 * al1 + ps1;
        m0 = nm0; m1 = nm1;
#pragma unroll
        for (int nt = 0; nt < 8; nt++) {
            o[nt][0] *= al0; o[nt][1] *= al0;
            o[nt][2] *= al1; o[nt][3] *= al1;
        }
        __syncwarp();

        // O += P @ V
#pragma unroll
        for (int s = 0; s < 8; s++) {
            unsigned pa[4];
            const float* pp = &PsW[g * AT_S + 8 * s + t];
            pa[0] = f2u(pp[0]);
            pa[1] = f2u(pp[8 * AT_S]);
            pa[2] = f2u(pp[4]);
            pa[3] = f2u(pp[8 * AT_S + 4]);
            const float* vp = &Vs[(8 * s + t) * AT_S + g];
#pragma unroll
            for (int nt = 0; nt < 8; nt++) {
                unsigned vb[2];
                vb[0] = f2u(vp[nt * 8]);
                vb[1] = f2u(vp[4 * AT_S + nt * 8]);
                mma8(o[nt], pa, vb);
            }
        }
        __syncthreads();
    }

    float i0 = 1.0f / l0, i1 = 1.0f / l1;
    int row0 = q0 + warp * 16 + g;
    float* outb = ctx + (size_t)(b * 1024) * 768 + h * 64;
#pragma unroll
    for (int nt = 0; nt < 8; nt++) {
        int col = nt * 8 + 2 * t;
        *(float2*)(outb + (size_t)row0 * 768 + col) =
            make_float2(to_tf32(o[nt][0] * i0), to_tf32(o[nt][1] * i0));
        *(float2*)(outb + (size_t)(row0 + 8) * 768 + col) =
            make_float2(to_tf32(o[nt][2] * i1), to_tf32(o[nt][3] * i1));
    }
}

// ---------------------------------------------------------------------------
// Host launch (graph-capturable)
// ---------------------------------------------------------------------------
extern "C" void kernel_launch(void* const* d_in, const int* in_sizes, int n_in,
                              void* d_out, int out_size)
{
    const float* x      = (const float*)d_in[0];
    const float* ln1_g  = (const float*)d_in[1];
    const float* ln1_b  = (const float*)d_in[2];
    const float* qkv_w  = (const float*)d_in[3];
    const float* qkv_b  = (const float*)d_in[4];
    const float* proj_w = (const float*)d_in[5];
    const float* proj_b = (const float*)d_in[6];
    const float* ln2_g  = (const float*)d_in[7];
    const float* ln2_b  = (const float*)d_in[8];
    const float* fc1_w  = (const float*)d_in[9];
    const float* fc1_b  = (const float*)d_in[10];
    const float* fc2_w  = (const float*)d_in[11];
    const float* fc2_b  = (const float*)d_in[12];
    const float* ln3_g  = (const float*)d_in[13];
    const float* ln3_b  = (const float*)d_in[14];
    float* out = (float*)d_out;

    float *xn1, *qkv, *ctx, *x2, *ffin, *hid, *x3, *wq, *wp, *w1, *w2;
    cudaGetSymbolAddress((void**)&xn1,  g_xn1);
    cudaGetSymbolAddress((void**)&qkv,  g_qkv);
    cudaGetSymbolAddress((void**)&ctx,  g_ctx);
    cudaGetSymbolAddress((void**)&x2,   g_x2);
    cudaGetSymbolAddress((void**)&ffin, g_ffin);
    cudaGetSymbolAddress((void**)&hid,  g_hid);
    cudaGetSymbolAddress((void**)&x3,   g_x3);
    cudaGetSymbolAddress((void**)&wq,   g_wq);
    cudaGetSymbolAddress((void**)&wp,   g_wp);
    cudaGetSymbolAddress((void**)&w1,   g_w1);
    cudaGetSymbolAddress((void**)&w2,   g_w2);

    cudaFuncSetAttribute(gemm_tf32<0>, cudaFuncAttributeMaxDynamicSharedMemorySize, GEMM_SMEM);
    cudaFuncSetAttribute(gemm_tf32<1>, cudaFuncAttributeMaxDynamicSharedMemorySize, GEMM_SMEM);
    cudaFuncSetAttribute(gemm_tf32<2>, cudaFuncAttributeMaxDynamicSharedMemorySize, GEMM_SMEM);
    cudaFuncSetAttribute(attn_tf32, cudaFuncAttributeMaxDynamicSharedMemorySize, ATT_SMEM);

    const int T = T_TOK;

    // pre-round weights to tf32
    round4_kernel<<<(768 * 2304 / 4 + 255) / 256, 256>>>(qkv_w, wq, 768 * 2304 / 4);
    round4_kernel<<<(768 * 768 / 4 + 255) / 256, 256>>>(proj_w, wp, 768 * 768 / 4);
    round4_kernel<<<(768 * 3072 / 4 + 255) / 256, 256>>>(fc1_w, w1, 768 * 3072 / 4);
    round4_kernel<<<(3072 * 768 / 4 + 255) / 256, 256>>>(fc2_w, w2, 3072 * 768 / 4);

    // 1) xn1 = LN1(x) [tf32-rounded]
    ln_kernel<true><<<T, 256>>>(x, ln1_g, ln1_b, xn1);
    // 2) qkv = xn1 @ qkv_w + qkv_b
    gemm_tf32<0><<<dim3(18, 128), 256, GEMM_SMEM>>>(xn1, wq, qkv_b, nullptr, qkv, T, 2304, 768);
    // 3) ctx = attention(qkv) [tf32-rounded]
    attn_tf32<<<dim3(16, 192), 128, ATT_SMEM>>>(qkv, ctx);
    // 4) x2 = x + ctx @ proj_w + proj_b
    gemm_tf32<2><<<dim3(6, 128), 256, GEMM_SMEM>>>(ctx, wp, proj_b, x, x2, T, 768, 768);
    // 5) ffin = LN2(x2) [tf32-rounded]
    ln_kernel<true><<<T, 256>>>(x2, ln2_g, ln2_b, ffin);
    // 6) hid = gelu(ffin @ fc1_w + fc1_b) [tf32-rounded]
    gemm_tf32<1><<<dim3(24, 128), 256, GEMM_SMEM>>>(ffin, w1, fc1_b, nullptr, hid, T, 3072, 768);
    // 7) x3 = ffin + hid @ fc2_w + fc2_b
    gemm_tf32<2><<<dim3(6, 128), 256, GEMM_SMEM>>>(hid, w2, fc2_b, ffin, x3, T, 768, 3072);
    // 8) out = LN3(x3)
    ln_kernel<false><<<T, 256>>>(x3, ln3_g, ln3_b, out);
}

// round 4
// speedup vs baseline: 4.7835x; 1.1251x over previous
#include <cuda_runtime.h>
#include <math.h>

// ---------------------------------------------------------------------------
// EncoderBlock: B=16, N=1024, DIM=768, HEADS=12, HEAD_DIM=64, HIDDEN=3072
// T = 16384 tokens. All matmuls on tensor pipe via mma.sync tf32.
// (tcgen05 unavailable: harness PTX target is sm_103 without 'a' features.)
// ---------------------------------------------------------------------------

#define T_TOK 16384

// Scratch (device globals: allocation-guard safe)
__device__ float g_xn1 [T_TOK * 768];
__device__ float g_qkv [T_TOK * 2304];
__device__ float g_ctx [T_TOK * 768];
__device__ float g_x2  [T_TOK * 768];
__device__ float g_ffin[T_TOK * 768];
__device__ float g_hid [T_TOK * 3072];
__device__ float g_x3  [T_TOK * 768];
// tf32-rounded weights
__device__ float g_wq  [768 * 2304];
__device__ float g_wp  [768 * 768];
__device__ float g_w1  [768 * 3072];
__device__ float g_w2  [3072 * 768];

// ---------------------------------------------------------------------------
// helpers
// ---------------------------------------------------------------------------
__device__ __forceinline__ unsigned f2u(float x) { return __float_as_uint(x); }

__device__ __forceinline__ float to_tf32(float x) {
    unsigned u;
    asm("cvt.rna.tf32.f32 %0, %1;" : "=r"(u) : "f"(x));
    return __uint_as_float(u);
}

__device__ __forceinline__ void mma8(float* c, const unsigned* a, const unsigned* b) {
    asm volatile(
        "mma.sync.aligned.m16n8k8.row.col.f32.tf32.tf32.f32 "
        "{%0,%1,%2,%3}, {%4,%5,%6,%7}, {%8,%9}, {%0,%1,%2,%3};\n"
        : "+f"(c[0]), "+f"(c[1]), "+f"(c[2]), "+f"(c[3])
        : "r"(a[0]), "r"(a[1]), "r"(a[2]), "r"(a[3]), "r"(b[0]), "r"(b[1]));
}

__device__ __forceinline__ void cp16(float* dst, const float* src) {
    unsigned d = (unsigned)__cvta_generic_to_shared(dst);
    asm volatile("cp.async.cg.shared.global [%0], [%1], 16;\n" :: "r"(d), "l"(src));
}
__device__ __forceinline__ void cp_commit() { asm volatile("cp.async.commit_group;\n"); }
template <int N>
__device__ __forceinline__ void cp_wait() { asm volatile("cp.async.wait_group %0;\n" :: "n"(N)); }

// ---------------------------------------------------------------------------
// weight pre-round to tf32 (rna)
// ---------------------------------------------------------------------------
__global__ __launch_bounds__(256) void round4_kernel(const float* __restrict__ in,
                                                     float* __restrict__ out, int n4)
{
    int i = blockIdx.x * 256 + threadIdx.x;
    if (i < n4) {
        float4 v = ((const float4*)in)[i];
        v.x = to_tf32(v.x); v.y = to_tf32(v.y); v.z = to_tf32(v.z); v.w = to_tf32(v.w);
        ((float4*)out)[i] = v;
    }
}

// ---------------------------------------------------------------------------
// LayerNorm over 768. ROUND: round output to tf32 (feeds a GEMM A operand).
// ---------------------------------------------------------------------------
template <bool ROUND>
__global__ __launch_bounds__(256) void ln_kernel(
    const float* __restrict__ in, const float* __restrict__ g,
    const float* __restrict__ b, float* __restrict__ out)
{
    int row = blockIdx.x;
    const float* p = in + (size_t)row * 768;
    float v[3];
    float s = 0.f, ss = 0.f;
#pragma unroll
    for (int i = 0; i < 3; i++) {
        v[i] = p[threadIdx.x + i * 256];
        s += v[i]; ss += v[i] * v[i];
    }
#pragma unroll
    for (int o = 16; o > 0; o >>= 1) {
        s  += __shfl_xor_sync(0xffffffffu, s,  o);
        ss += __shfl_xor_sync(0xffffffffu, ss, o);
    }
    __shared__ float rs[8], rss[8];
    int w = threadIdx.x >> 5, lane = threadIdx.x & 31;
    if (lane == 0) { rs[w] = s; rss[w] = ss; }
    __syncthreads();
    s = 0.f; ss = 0.f;
#pragma unroll
    for (int i = 0; i < 8; i++) { s += rs[i]; ss += rss[i]; }
    float mean = s * (1.0f / 768.0f);
    float var  = ss * (1.0f / 768.0f) - mean * mean;
    float rstd = rsqrtf(var + 1e-5f);
    float* q = out + (size_t)row * 768;
#pragma unroll
    for (int i = 0; i < 3; i++) {
        int c = threadIdx.x + i * 256;
        float r = (v[i] - mean) * rstd * g[c] + b[c];
        q[c] = ROUND ? to_tf32(r) : r;
    }
}

// ---------------------------------------------------------------------------
// tf32 mma GEMM v2: C[M,N] = A[M,K] @ B[K,N] + bias, epilogue:
//   EPI=0: none; EPI=1: exact GELU then tf32-round; EPI=2: += res
// 128x256x32 CTA tile, 256 threads (8 warps, 2m x 4n), warp tile 64x64.
// Per k-step: 32 LDS feeds 32 mma (1.0 LDS/mma, conflict-free strides).
// ---------------------------------------------------------------------------
#define GA_S 36
#define GB_S 260
#define GA_BUF (128 * GA_S)
#define GB_BUF (32 * GB_S)
#define GEMM_SMEM ((2 * GA_BUF + 2 * GB_BUF) * 4)

template <int EPI>
__global__ __launch_bounds__(256) void gemm_tf32(
    const float* __restrict__ A, const float* __restrict__ B,
    const float* __restrict__ bias, const float* __restrict__ res,
    float* __restrict__ C, int M, int N, int K)
{
    extern __shared__ float smx[];
    float* As = smx;                // [2][128][GA_S]
    float* Bs = smx + 2 * GA_BUF;   // [2][32][GB_S]

    int tid = threadIdx.x;
    int warp = tid >> 5, lane = tid & 31;
    int g = lane >> 2, t = lane & 3;
    int wm = (warp & 1) * 64, wn = (warp >> 1) * 64;
    int bm = blockIdx.y * 128, bn = blockIdx.x * 256;

    int ar = tid >> 3, ac = (tid & 7) * 4;    // A copy: 128 rows x 32 cols
    int br = tid >> 6, bc = (tid & 63) * 4;   // B copy: 32 rows x 256 cols

    float acc[4][8][4];
#pragma unroll
    for (int i = 0; i < 4; i++)
#pragma unroll
        for (int j = 0; j < 8; j++)
#pragma unroll
            for (int q = 0; q < 4; q++) acc[i][j][q] = 0.f;

    const float* Agb = A + (size_t)bm * K;
    const float* Bgb = B + bn;

    // prologue: k-tile 0 into buf 0
    {
#pragma unroll
        for (int i = 0; i < 4; i++) {
            int idx = tid + i * 256;
            int r = idx >> 3, c = (idx & 7) * 4;
            cp16(&As[r * GA_S + c], Agb + (size_t)r * K + c);
        }
#pragma unroll
        for (int i = 0; i < 8; i++) {
            int r = br + 4 * i;
            cp16(&Bs[r * GB_S + bc], Bgb + (size_t)r * N + bc);
        }
        cp_commit();
    }

    int ntile = K >> 5;
    for (int tt = 0; tt < ntile; tt++) {
        if (tt + 1 < ntile) {
            int buf = (tt + 1) & 1;
            int k0 = (tt + 1) * 32;
            float* Ab = As + buf * GA_BUF;
            float* Bb = Bs + buf * GB_BUF;
#pragma unroll
            for (int i = 0; i < 4; i++) {
                int idx = tid + i * 256;
                int r = idx >> 3, c = (idx & 7) * 4;
                cp16(&Ab[r * GA_S + c], Agb + (size_t)r * K + k0 + c);
            }
#pragma unroll
            for (int i = 0; i < 8; i++) {
                int r = br + 4 * i;
                cp16(&Bb[r * GB_S + bc], Bgb + (size_t)(k0 + r) * N + bc);
            }
            cp_commit();
            cp_wait<1>();
        } else {
            cp_wait<0>();
        }
        __syncthreads();

        int buf = tt & 1;
        const float* Abase = &As[buf * GA_BUF + (wm + g) * GA_S + t];
        const float* Bbase = &Bs[buf * GB_BUF + t * GB_S + wn + g];
#pragma unroll
        for (int s = 0; s < 4; s++) {
            unsigned a[4][4], b[8][2];
#pragma unroll
            for (int mt = 0; mt < 4; mt++) {
                const float* p = Abase + mt * 16 * GA_S + 8 * s;
                a[mt][0] = f2u(p[0]);
                a[mt][1] = f2u(p[8 * GA_S]);
                a[mt][2] = f2u(p[4]);
                a[mt][3] = f2u(p[8 * GA_S + 4]);
            }
#pragma unroll
            for (int nt = 0; nt < 8; nt++) {
                const float* p = Bbase + (8 * s) * GB_S + nt * 8;
                b[nt][0] = f2u(p[0]);
                b[nt][1] = f2u(p[4 * GB_S]);
            }
#pragma unroll
            for (int mt = 0; mt < 4; mt++)
#pragma unroll
                for (int nt = 0; nt < 8; nt++)
                    mma8(acc[mt][nt], a[mt], b[nt]);
        }
        __syncthreads();
    }

    // epilogue
#pragma unroll
    for (int mt = 0; mt < 4; mt++) {
        int r0 = bm + wm + mt * 16 + g;
        int r1 = r0 + 8;
#pragma unroll
        for (int nt = 0; nt < 8; nt++) {
            int col = bn + wn + nt * 8 + 2 * t;
            float b0 = bias[col], b1 = bias[col + 1];
            float v0 = acc[mt][nt][0] + b0, v1 = acc[mt][nt][1] + b1;
            float v2 = acc[mt][nt][2] + b0, v3 = acc[mt][nt][3] + b1;
            if (EPI == 1) {
                v0 = to_tf32(0.5f * v0 * (1.0f + erff(v0 * 0.70710678118654752f)));
                v1 = to_tf32(0.5f * v1 * (1.0f + erff(v1 * 0.70710678118654752f)));
                v2 = to_tf32(0.5f * v2 * (1.0f + erff(v2 * 0.70710678118654752f)));
                v3 = to_tf32(0.5f * v3 * (1.0f + erff(v3 * 0.70710678118654752f)));
            }
            if (EPI == 2) {
                float2 ra = *(const float2*)(res + (size_t)r0 * N + col);
                float2 rb = *(const float2*)(res + (size_t)r1 * N + col);
                v0 += ra.x; v1 += ra.y; v2 += rb.x; v3 += rb.y;
            }
            *(float2*)(C + (size_t)r0 * N + col) = make_float2(v0, v1);
            *(float2*)(C + (size_t)r1 * N + col) = make_float2(v2, v3);
        }
    }
}

// ---------------------------------------------------------------------------
// Flash attention with tf32 mma. Br=64, Bc=64, 128 threads (4 warps).
// ---------------------------------------------------------------------------
#define AT_S 76
#define ATT_SMEM (3 * 64 * AT_S * 4)

__global__ __launch_bounds__(128) void attn_tf32(
    const float* __restrict__ qkv, float* __restrict__ ctx)
{
    extern __shared__ float smx[];
    float* QPs = smx;                 // 64 x AT_S : Q then reused as P
    float* Ks  = smx + 64 * AT_S;
    float* Vs  = smx + 2 * 64 * AT_S;

    int tid = threadIdx.x, warp = tid >> 5, lane = tid & 31;
    int g = lane >> 2, t = lane & 3;
    int bh = blockIdx.y, b = bh / 12, h = bh % 12;
    size_t base = (size_t)b * 1024 * 2304 + h * 64;
    int q0 = blockIdx.x * 64;

#pragma unroll
    for (int i = 0; i < 8; i++) {
        int idx = tid + i * 128;
        int r = idx >> 4, c = (idx & 15) * 4;
        float4 v = *(const float4*)(qkv + base + (size_t)(q0 + r) * 2304 + c);
        v.x *= 0.125f; v.y *= 0.125f; v.z *= 0.125f; v.w *= 0.125f;
        *(float4*)&QPs[r * AT_S + c] = v;
    }
    __syncthreads();

    unsigned qa[8][4];
    {
        const float* p0 = &QPs[(warp * 16 + g) * AT_S + t];
#pragma unroll
        for (int s = 0; s < 8; s++) {
            qa[s][0] = f2u(p0[8 * s]);
            qa[s][1] = f2u(p0[8 * AT_S + 8 * s]);
            qa[s][2] = f2u(p0[8 * s + 4]);
            qa[s][3] = f2u(p0[8 * AT_S + 8 * s + 4]);
        }
    }
    __syncthreads();   // QPs now free -> P buffer

    float* PsW = QPs + warp * 16 * AT_S;

    float o[8][4];
#pragma unroll
    for (int i = 0; i < 8; i++)
#pragma unroll
        for (int j = 0; j < 4; j++) o[i][j] = 0.f;
    float m0 = -1e30f, m1 = -1e30f, l0 = 0.f, l1 = 0.f;

    for (int kt = 0; kt < 16; kt++) {
#pragma unroll
        for (int i = 0; i < 8; i++) {
            int idx = tid + i * 128;
            int r = idx >> 4, c = (idx & 15) * 4;
            const float* kp = qkv + base + (size_t)(kt * 64 + r) * 2304 + 768 + c;
            *(float4*)&Ks[r * AT_S + c] = *(const float4*)kp;
            *(float4*)&Vs[r * AT_S + c] = *(const float4*)(kp + 768);
        }
        __syncthreads();

        float sc[8][4];
#pragma unroll
        for (int i = 0; i < 8; i++)
#pragma unroll
            for (int j = 0; j < 4; j++) sc[i][j] = 0.f;
#pragma unroll
        for (int s = 0; s < 8; s++) {
            const float* Kb = &Ks[g * AT_S + 8 * s + t];
#pragma unroll
            for (int nt = 0; nt < 8; nt++) {
                unsigned bb[2];
                const float* p = Kb + nt * 8 * AT_S;
                bb[0] = f2u(p[0]);
                bb[1] = f2u(p[4]);
                mma8(sc[nt], qa[s], bb);
            }
        }

        float mx0 = -1e30f, mx1 = -1e30f;
#pragma unroll
        for (int nt = 0; nt < 8; nt++) {
            mx0 = fmaxf(mx0, fmaxf(sc[nt][0], sc[nt][1]));
            mx1 = fmaxf(mx1, fmaxf(sc[nt][2], sc[nt][3]));
        }
        mx0 = fmaxf(mx0, __shfl_xor_sync(0xffffffffu, mx0, 1));
        mx0 = fmaxf(mx0, __shfl_xor_sync(0xffffffffu, mx0, 2));
        mx1 = fmaxf(mx1, __shfl_xor_sync(0xffffffffu, mx1, 1));
        mx1 = fmaxf(mx1, __shfl_xor_sync(0xffffffffu, mx1, 2));
        float nm0 = fmaxf(m0, mx0), nm1 = fmaxf(m1, mx1);
        float al0 = __expf(m0 - nm0), al1 = __expf(m1 - nm1);
        float ps0 = 0.f, ps1 = 0.f;
#pragma unroll
        for (int nt = 0; nt < 8; nt++) {
            float p0 = __expf(sc[nt][0] - nm0);
            float p1 = __expf(sc[nt][1] - nm0);
            float p2 = __expf(sc[nt][2] - nm1);
            float p3 = __expf(sc[nt][3] - nm1);
            ps0 += p0 + p1; ps1 += p2 + p3;
            *(float2*)&PsW[g * AT_S + nt * 8 + 2 * t]       = make_float2(p0, p1);
            *(float2*)&PsW[(g + 8) * AT_S + nt * 8 + 2 * t] = make_float2(p2, p3);
        }
        ps0 += __shfl_xor_sync(0xffffffffu, ps0, 1);
        ps0 += __shfl_xor_sync(0xffffffffu, ps0, 2);
        ps1 += __shfl_xor_sync(0xffffffffu, ps1, 1);
        ps1 += __shfl_xor_sync(0xffffffffu, ps1, 2);
        l0 = l0 * al0 + ps0;
        l1 = l1 * al1 + ps1;
        m0 = nm0; m1 = nm1;
#pragma unroll
        for (int nt = 0; nt < 8; nt++) {
            o[nt][0] *= al0; o[nt][1] *= al0;
            o[nt][2] *= al1; o[nt][3] *= al1;
        }
        __syncwarp();

#pragma unroll
        for (int s = 0; s < 8; s++) {
            unsigned pa[4];
            const float* pp = &PsW[g * AT_S + 8 * s + t];
            pa[0] = f2u(pp[0]);
            pa[1] = f2u(pp[8 * AT_S]);
            pa[2] = f2u(pp[4]);
            pa[3] = f2u(pp[8 * AT_S + 4]);
            const float* vp = &Vs[(8 * s + t) * AT_S + g];
#pragma unroll
            for (int nt = 0; nt < 8; nt++) {
                unsigned vb[2];
                vb[0] = f2u(vp[nt * 8]);
                vb[1] = f2u(vp[4 * AT_S + nt * 8]);
                mma8(o[nt], pa, vb);
            }
        }
        __syncthreads();
    }

    float i0 = 1.0f / l0, i1 = 1.0f / l1;
    int row0 = q0 + warp * 16 + g;
    float* outb = ctx + (size_t)(b * 1024) * 768 + h * 64;
#pragma unroll
    for (int nt = 0; nt < 8; nt++) {
        int col = nt * 8 + 2 * t;
        *(float2*)(outb + (size_t)row0 * 768 + col) =
            make_float2(to_tf32(o[nt][0] * i0), to_tf32(o[nt][1] * i0));
        *(float2*)(outb + (size_t)(row0 + 8) * 768 + col) =
            make_float2(to_tf32(o[nt][2] * i1), to_tf32(o[nt][3] * i1));
    }
}

// ---------------------------------------------------------------------------
// Host launch (graph-capturable)
// ---------------------------------------------------------------------------
extern "C" void kernel_launch(void* const* d_in, const int* in_sizes, int n_in,
                              void* d_out, int out_size)
{
    const float* x      = (const float*)d_in[0];
    const float* ln1_g  = (const float*)d_in[1];
    const float* ln1_b  = (const float*)d_in[2];
    const float* qkv_w  = (const float*)d_in[3];
    const float* qkv_b  = (const float*)d_in[4];
    const float* proj_w = (const float*)d_in[5];
    const float* proj_b = (const float*)d_in[6];
    const float* ln2_g  = (const float*)d_in[7];
    const float* ln2_b  = (const float*)d_in[8];
    const float* fc1_w  = (const float*)d_in[9];
    const float* fc1_b  = (const float*)d_in[10];
    const float* fc2_w  = (const float*)d_in[11];
    const float* fc2_b  = (const float*)d_in[12];
    const float* ln3_g  = (const float*)d_in[13];
    const float* ln3_b  = (const float*)d_in[14];
    float* out = (float*)d_out;

    float *xn1, *qkv, *ctx, *x2, *ffin, *hid, *x3, *wq, *wp, *w1, *w2;
    cudaGetSymbolAddress((void**)&xn1,  g_xn1);
    cudaGetSymbolAddress((void**)&qkv,  g_qkv);
    cudaGetSymbolAddress((void**)&ctx,  g_ctx);
    cudaGetSymbolAddress((void**)&x2,   g_x2);
    cudaGetSymbolAddress((void**)&ffin, g_ffin);
    cudaGetSymbolAddress((void**)&hid,  g_hid);
    cudaGetSymbolAddress((void**)&x3,   g_x3);
    cudaGetSymbolAddress((void**)&wq,   g_wq);
    cudaGetSymbolAddress((void**)&wp,   g_wp);
    cudaGetSymbolAddress((void**)&w1,   g_w1);
    cudaGetSymbolAddress((void**)&w2,   g_w2);

    cudaFuncSetAttribute(gemm_tf32<0>, cudaFuncAttributeMaxDynamicSharedMemorySize, GEMM_SMEM);
    cudaFuncSetAttribute(gemm_tf32<1>, cudaFuncAttributeMaxDynamicSharedMemorySize, GEMM_SMEM);
    cudaFuncSetAttribute(gemm_tf32<2>, cudaFuncAttributeMaxDynamicSharedMemorySize, GEMM_SMEM);
    cudaFuncSetAttribute(attn_tf32, cudaFuncAttributeMaxDynamicSharedMemorySize, ATT_SMEM);

    const int T = T_TOK;

    // pre-round weights to tf32
    round4_kernel<<<(768 * 2304 / 4 + 255) / 256, 256>>>(qkv_w, wq, 768 * 2304 / 4);
    round4_kernel<<<(768 * 768 / 4 + 255) / 256, 256>>>(proj_w, wp, 768 * 768 / 4);
    round4_kernel<<<(768 * 3072 / 4 + 255) / 256, 256>>>(fc1_w, w1, 768 * 3072 / 4);
    round4_kernel<<<(3072 * 768 / 4 + 255) / 256, 256>>>(fc2_w, w2, 3072 * 768 / 4);

    // 1) xn1 = LN1(x) [tf32-rounded]
    ln_kernel<true><<<T, 256>>>(x, ln1_g, ln1_b, xn1);
    // 2) qkv = xn1 @ qkv_w + qkv_b
    gemm_tf32<0><<<dim3(9, 128), 256, GEMM_SMEM>>>(xn1, wq, qkv_b, nullptr, qkv, T, 2304, 768);
    // 3) ctx = attention(qkv) [tf32-rounded]
    attn_tf32<<<dim3(16, 192), 128, ATT_SMEM>>>(qkv, ctx);
    // 4) x2 = x + ctx @ proj_w + proj_b
    gemm_tf32<2><<<dim3(3, 128), 256, GEMM_SMEM>>>(ctx, wp, proj_b, x, x2, T, 768, 768);
    // 5) ffin = LN2(x2) [tf32-rounded]
    ln_kernel<true><<<T, 256>>>(x2, ln2_g, ln2_b, ffin);
    // 6) hid = gelu(ffin @ fc1_w + fc1_b) [tf32-rounded]
    gemm_tf32<1><<<dim3(12, 128), 256, GEMM_SMEM>>>(ffin, w1, fc1_b, nullptr, hid, T, 3072, 768);
    // 7) x3 = ffin + hid @ fc2_w + fc2_b
    gemm_tf32<2><<<dim3(3, 128), 256, GEMM_SMEM>>>(hid, w2, fc2_b, ffin, x3, T, 768, 3072);
    // 8) out = LN3(x3)
    ln_kernel<false><<<T, 256>>>(x3, ln3_g, ln3_b, out);
}

// round 5
// speedup vs baseline: 8.1040x; 1.6942x over previous
#include <cuda_runtime.h>
#include <cuda_fp16.h>
#include <math.h>
#include <stdint.h>

// ---------------------------------------------------------------------------
// EncoderBlock: B=16, N=1024, DIM=768, HEADS=12, HEAD_DIM=64, HIDDEN=3072
// T = 16384 tokens. All matmuls: mma.sync m16n8k16 fp16 (fp32 accumulate).
// fp16 mantissa == tf32 mantissa (10 bits) -> same accuracy as rounds 2/4.
// ---------------------------------------------------------------------------

#define T_TOK 16384

// Scratch (device globals: allocation-guard safe)
__device__ __half g_xn1 [T_TOK * 768];
__device__ __half g_qkv [T_TOK * 2304];
__device__ __half g_ctx [T_TOK * 768];
__device__ float  g_x2  [T_TOK * 768];
__device__ __half g_ffin[T_TOK * 768];
__device__ __half g_hid [T_TOK * 3072];
__device__ float  g_x3  [T_TOK * 768];
// transposed fp16 weights Wt[N,K]
__device__ __half g_wq  [2304 * 768];
__device__ __half g_wp  [768 * 768];
__device__ __half g_w1  [3072 * 768];
__device__ __half g_w2  [768 * 3072];

// ---------------------------------------------------------------------------
// helpers
// ---------------------------------------------------------------------------
__device__ __forceinline__ void mma16(float* c, const unsigned* a, const unsigned* b) {
    asm volatile(
        "mma.sync.aligned.m16n8k16.row.col.f32.f16.f16.f32 "
        "{%0,%1,%2,%3}, {%4,%5,%6,%7}, {%8,%9}, {%0,%1,%2,%3};\n"
        : "+f"(c[0]), "+f"(c[1]), "+f"(c[2]), "+f"(c[3])
        : "r"(a[0]), "r"(a[1]), "r"(a[2]), "r"(a[3]), "r"(b[0]), "r"(b[1]));
}

__device__ __forceinline__ void ldsm4t(unsigned& r0, unsigned& r1, unsigned& r2,
                                       unsigned& r3, uint32_t addr) {
    asm volatile("ldmatrix.sync.aligned.m8n8.x4.trans.shared.b16 {%0,%1,%2,%3}, [%4];"
                 : "=r"(r0), "=r"(r1), "=r"(r2), "=r"(r3) : "r"(addr));
}

__device__ __forceinline__ void cp16(__half* dst, const __half* src) {
    unsigned d = (unsigned)__cvta_generic_to_shared(dst);
    asm volatile("cp.async.cg.shared.global [%0], [%1], 16;\n" :: "r"(d), "l"(src));
}
__device__ __forceinline__ void cp_commit() { asm volatile("cp.async.commit_group;\n"); }
template <int N>
__device__ __forceinline__ void cp_wait() { asm volatile("cp.async.wait_group %0;\n" :: "n"(N)); }

// ---------------------------------------------------------------------------
// weight transpose + fp16 round: W[K,N] -> Wt[N,K] half
// ---------------------------------------------------------------------------
__global__ __launch_bounds__(256) void transpose_half(
    const float* __restrict__ in, __half* __restrict__ out, int K, int N)
{
    __shared__ float s[32][33];
    int n0 = blockIdx.x * 32, k0 = blockIdx.y * 32;
    int tx = threadIdx.x & 31, ty = threadIdx.x >> 5;
#pragma unroll
    for (int j = 0; j < 4; j++)
        s[ty + 8 * j][tx] = in[(size_t)(k0 + ty + 8 * j) * N + n0 + tx];
    __syncthreads();
#pragma unroll
    for (int j = 0; j < 4; j++)
        out[(size_t)(n0 + ty + 8 * j) * K + k0 + tx] = __float2half_rn(s[tx][ty + 8 * j]);
}

// ---------------------------------------------------------------------------
// LayerNorm over 768. OUTH: write half (GEMM A operand) else float.
// ---------------------------------------------------------------------------
template <int OUTH>
__global__ __launch_bounds__(256) void ln_kernel(
    const float* __restrict__ in, const float* __restrict__ g,
    const float* __restrict__ b, void* __restrict__ outv)
{
    int row = blockIdx.x;
    const float* p = in + (size_t)row * 768;
    float v[3];
    float s = 0.f, ss = 0.f;
#pragma unroll
    for (int i = 0; i < 3; i++) {
        v[i] = p[threadIdx.x + i * 256];
        s += v[i]; ss += v[i] * v[i];
    }
#pragma unroll
    for (int o = 16; o > 0; o >>= 1) {
        s  += __shfl_xor_sync(0xffffffffu, s,  o);
        ss += __shfl_xor_sync(0xffffffffu, ss, o);
    }
    __shared__ float rs[8], rss[8];
    int w = threadIdx.x >> 5, lane = threadIdx.x & 31;
    if (lane == 0) { rs[w] = s; rss[w] = ss; }
    __syncthreads();
    s = 0.f; ss = 0.f;
#pragma unroll
    for (int i = 0; i < 8; i++) { s += rs[i]; ss += rss[i]; }
    float mean = s * (1.0f / 768.0f);
    float var  = ss * (1.0f / 768.0f) - mean * mean;
    float rstd = rsqrtf(var + 1e-5f);
#pragma unroll
    for (int i = 0; i < 3; i++) {
        int c = threadIdx.x + i * 256;
        float r = (v[i] - mean) * rstd * g[c] + b[c];
        if (OUTH) ((__half*)outv)[(size_t)row * 768 + c] = __float2half_rn(r);
        else      ((float*)outv)[(size_t)row * 768 + c] = r;
    }
}

// ---------------------------------------------------------------------------
// fp16 mma GEMM: C[M,N] = A[M,K] @ W[K,N] + bias.  W given transposed Wt[N,K].
//   EPI=0 none | EPI=1 exact GELU | EPI=2 += res
//   OUTH: output half else float. RESH: residual half else float.
// 128x256x32 CTA tile, 256 threads (8 warps 2x4), warp tile 64x64.
// ---------------------------------------------------------------------------
#define AS_S 40
#define BS_S 40
#define GA_BUF (128 * AS_S)
#define GB_BUF (256 * BS_S)
#define GEMM_SMEM ((2 * GA_BUF + 2 * GB_BUF) * 2)

template <int EPI, int OUTH, int RESH>
__global__ __launch_bounds__(256) void gemm_f16(
    const __half* __restrict__ A, const __half* __restrict__ Bt,
    const float* __restrict__ bias, const void* __restrict__ resv,
    void* __restrict__ Cv, int M, int N, int K)
{
    extern __shared__ __half smh[];
    __half* As = smh;                 // [2][128][AS_S]
    __half* Bs = smh + 2 * GA_BUF;    // [2][256][BS_S]

    int tid = threadIdx.x;
    int warp = tid >> 5, lane = tid & 31;
    int g = lane >> 2, t = lane & 3;
    int wm = (warp & 1) * 64, wn = (warp >> 1) * 64;
    int bm = blockIdx.y * 128, bn = blockIdx.x * 256;

    float acc[4][8][4];
#pragma unroll
    for (int i = 0; i < 4; i++)
#pragma unroll
        for (int j = 0; j < 8; j++)
#pragma unroll
            for (int q = 0; q < 4; q++) acc[i][j][q] = 0.f;

    const __half* Agb = A + (size_t)bm * K;
    const __half* Bgb = Bt + (size_t)bn * K;

    // prologue: k-tile 0 -> buf 0
    {
#pragma unroll
        for (int i = 0; i < 2; i++) {
            int idx = tid + i * 256; int r = idx >> 2, c = (idx & 3) * 8;
            cp16(&As[r * AS_S + c], Agb + (size_t)r * K + c);
        }
#pragma unroll
        for (int i = 0; i < 4; i++) {
            int idx = tid + i * 256; int r = idx >> 2, c = (idx & 3) * 8;
            cp16(&Bs[r * BS_S + c], Bgb + (size_t)r * K + c);
        }
        cp_commit();
    }

    int ntile = K >> 5;
    for (int tt = 0; tt < ntile; tt++) {
        if (tt + 1 < ntile) {
            int nb = (tt + 1) & 1;
            int k0 = (tt + 1) * 32;
            __half* Ab = As + nb * GA_BUF;
            __half* Bb = Bs + nb * GB_BUF;
#pragma unroll
            for (int i = 0; i < 2; i++) {
                int idx = tid + i * 256; int r = idx >> 2, c = (idx & 3) * 8;
                cp16(&Ab[r * AS_S + c], Agb + (size_t)r * K + k0 + c);
            }
#pragma unroll
            for (int i = 0; i < 4; i++) {
                int idx = tid + i * 256; int r = idx >> 2, c = (idx & 3) * 8;
                cp16(&Bb[r * BS_S + c], Bgb + (size_t)r * K + k0 + c);
            }
            cp_commit();
            cp_wait<1>();
        } else {
            cp_wait<0>();
        }
        __syncthreads();

        int buf = tt & 1;
        const __half* Abase = As + buf * GA_BUF + (wm + g) * AS_S + 2 * t;
        const __half* Bbase = Bs + buf * GB_BUF + (wn + g) * BS_S + 2 * t;
#pragma unroll
        for (int s = 0; s < 2; s++) {
            unsigned a[4][4], b[8][2];
#pragma unroll
            for (int mt = 0; mt < 4; mt++) {
                const __half* p = Abase + mt * 16 * AS_S + 16 * s;
                a[mt][0] = *(const unsigned*)(p);
                a[mt][1] = *(const unsigned*)(p + 8 * AS_S);
                a[mt][2] = *(const unsigned*)(p + 8);
                a[mt][3] = *(const unsigned*)(p + 8 * AS_S + 8);
            }
#pragma unroll
            for (int nt = 0; nt < 8; nt++) {
                const __half* p = Bbase + nt * 8 * BS_S + 16 * s;
                b[nt][0] = *(const unsigned*)(p);
                b[nt][1] = *(const unsigned*)(p + 8);
            }
#pragma unroll
            for (int mt = 0; mt < 4; mt++)
#pragma unroll
                for (int nt = 0; nt < 8; nt++)
                    mma16(acc[mt][nt], a[mt], b[nt]);
        }
        __syncthreads();
    }

    // epilogue
#pragma unroll
    for (int mt = 0; mt < 4; mt++) {
        int r0 = bm + wm + mt * 16 + g;
        int r1 = r0 + 8;
#pragma unroll
        for (int nt = 0; nt < 8; nt++) {
            int col = bn + wn + nt * 8 + 2 * t;
            float b0 = bias[col], b1 = bias[col + 1];
            float v0 = acc[mt][nt][0] + b0, v1 = acc[mt][nt][1] + b1;
            float v2 = acc[mt][nt][2] + b0, v3 = acc[mt][nt][3] + b1;
            if (EPI == 1) {
                v0 = 0.5f * v0 * (1.0f + erff(v0 * 0.70710678118654752f));
                v1 = 0.5f * v1 * (1.0f + erff(v1 * 0.70710678118654752f));
                v2 = 0.5f * v2 * (1.0f + erff(v2 * 0.70710678118654752f));
                v3 = 0.5f * v3 * (1.0f + erff(v3 * 0.70710678118654752f));
            }
            if (EPI == 2) {
                if (RESH) {
                    const __half* rh = (const __half*)resv;
                    float2 ra = __half22float2(*(const __half2*)(rh + (size_t)r0 * N + col));
                    float2 rb = __half22float2(*(const __half2*)(rh + (size_t)r1 * N + col));
                    v0 += ra.x; v1 += ra.y; v2 += rb.x; v3 += rb.y;
                } else {
                    const float* rf = (const float*)resv;
                    float2 ra = *(const float2*)(rf + (size_t)r0 * N + col);
                    float2 rb = *(const float2*)(rf + (size_t)r1 * N + col);
                    v0 += ra.x; v1 += ra.y; v2 += rb.x; v3 += rb.y;
                }
            }
            if (OUTH) {
                __half* Ch = (__half*)Cv;
                *(__half2*)(Ch + (size_t)r0 * N + col) = __floats2half2_rn(v0, v1);
                *(__half2*)(Ch + (size_t)r1 * N + col) = __floats2half2_rn(v2, v3);
            } else {
                float* Cf = (float*)Cv;
                *(float2*)(Cf + (size_t)r0 * N + col) = make_float2(v0, v1);
                *(float2*)(Cf + (size_t)r1 * N + col) = make_float2(v2, v3);
            }
        }
    }
}

// ---------------------------------------------------------------------------
// Flash attention fp16. Br=64, Bc=64, 128 threads (4 warps, 16 q-rows each).
// qkv half [T, 2304]: Q +0, K +768, V +1536 (head h: +h*64).
// S,O accumulate fp32; P half via smem; V B-frags via ldmatrix.x4.trans.
// ---------------------------------------------------------------------------
#define AT_S 72

__global__ __launch_bounds__(128) void attn_f16(
    const __half* __restrict__ qkv, __half* __restrict__ ctx)
{
    __shared__ __half sm[3 * 64 * AT_S];
    __half* QPs = sm;               // Q, later P
    __half* Ks  = sm + 64 * AT_S;
    __half* Vs  = sm + 2 * 64 * AT_S;
    uint32_t vs_base = (uint32_t)__cvta_generic_to_shared(Vs);

    int tid = threadIdx.x, warp = tid >> 5, lane = tid & 31;
    int g = lane >> 2, t = lane & 3;
    int bh = blockIdx.y, b = bh / 12, h = bh % 12;
    size_t base = (size_t)b * 1024 * 2304 + h * 64;
    int q0 = blockIdx.x * 64;

    // load Q (scaled by 1/8; exact power-of-two in half)
    __half2 s2 = __floats2half2_rn(0.125f, 0.125f);
#pragma unroll
    for (int i = 0; i < 4; i++) {
        int idx = tid + i * 128;
        int r = idx >> 3, c = (idx & 7) * 8;
        uint4 u = *(const uint4*)(qkv + base + (size_t)(q0 + r) * 2304 + c);
        __half2* hp = (__half2*)&u;
        hp[0] = __hmul2(hp[0], s2); hp[1] = __hmul2(hp[1], s2);
        hp[2] = __hmul2(hp[2], s2); hp[3] = __hmul2(hp[3], s2);
        *(uint4*)&QPs[r * AT_S + c] = u;
    }
    __syncthreads();

    // Q fragments in regs for whole kernel
    unsigned qa[4][4];
    {
        const __half* p0 = &QPs[(warp * 16 + g) * AT_S + 2 * t];
#pragma unroll
        for (int s = 0; s < 4; s++) {
            qa[s][0] = *(const unsigned*)(p0 + 16 * s);
            qa[s][1] = *(const unsigned*)(p0 + 16 * s + 8 * AT_S);
            qa[s][2] = *(const unsigned*)(p0 + 16 * s + 8);
            qa[s][3] = *(const unsigned*)(p0 + 16 * s + 8 * AT_S + 8);
        }
    }
    __syncthreads();   // QPs now free -> P buffer

    __half* PsW = QPs + warp * 16 * AT_S;

    float o[8][4];
#pragma unroll
    for (int i = 0; i < 8; i++)
#pragma unroll
        for (int j = 0; j < 4; j++) o[i][j] = 0.f;
    float m0 = -1e30f, m1 = -1e30f, l0 = 0.f, l1 = 0.f;

    // ldmatrix per-lane address precompute (row/col offsets within V tile)
    int lm_row = ((lane >> 3) & 1) * 8 + (lane & 7);
    int lm_col = ((lane >> 4) & 1) * 8;

    for (int kt = 0; kt < 16; kt++) {
        // load K, V tiles [64 keys x 64 dims]
#pragma unroll
        for (int i = 0; i < 4; i++) {
            int idx = tid + i * 128;
            int r = idx >> 3, c = (idx & 7) * 8;
            const __half* kp = qkv + base + (size_t)(kt * 64 + r) * 2304 + 768 + c;
            *(uint4*)&Ks[r * AT_S + c] = *(const uint4*)kp;
            *(uint4*)&Vs[r * AT_S + c] = *(const uint4*)(kp + 768);
        }
        __syncthreads();

        // S = Q K^T (Q pre-scaled)
        float sc[8][4];
#pragma unroll
        for (int i = 0; i < 8; i++)
#pragma unroll
            for (int j = 0; j < 4; j++) sc[i][j] = 0.f;
#pragma unroll
        for (int s = 0; s < 4; s++) {
            unsigned bb[8][2];
#pragma unroll
            for (int nt = 0; nt < 8; nt++) {
                const __half* p = &Ks[(nt * 8 + g) * AT_S + 16 * s + 2 * t];
                bb[nt][0] = *(const unsigned*)(p);
                bb[nt][1] = *(const unsigned*)(p + 8);
            }
#pragma unroll
            for (int nt = 0; nt < 8; nt++)
                mma16(sc[nt], qa[s], bb[nt]);
        }

        // online softmax (rows g, g+8 of warp strip)
        float mx0 = -1e30f, mx1 = -1e30f;
#pragma unroll
        for (int nt = 0; nt < 8; nt++) {
            mx0 = fmaxf(mx0, fmaxf(sc[nt][0], sc[nt][1]));
            mx1 = fmaxf(mx1, fmaxf(sc[nt][2], sc[nt][3]));
        }
        mx0 = fmaxf(mx0, __shfl_xor_sync(0xffffffffu, mx0, 1));
        mx0 = fmaxf(mx0, __shfl_xor_sync(0xffffffffu, mx0, 2));
        mx1 = fmaxf(mx1, __shfl_xor_sync(0xffffffffu, mx1, 1));
        mx1 = fmaxf(mx1, __shfl_xor_sync(0xffffffffu, mx1, 2));
        float nm0 = fmaxf(m0, mx0), nm1 = fmaxf(m1, mx1);
        float al0 = __expf(m0 - nm0), al1 = __expf(m1 - nm1);
        float ps0 = 0.f, ps1 = 0.f;
#pragma unroll
        for (int nt = 0; nt < 8; nt++) {
            float p0 = __expf(sc[nt][0] - nm0);
            float p1 = __expf(sc[nt][1] - nm0);
            float p2 = __expf(sc[nt][2] - nm1);
            float p3 = __expf(sc[nt][3] - nm1);
            ps0 += p0 + p1; ps1 += p2 + p3;
            *(__half2*)&PsW[g * AT_S + nt * 8 + 2 * t]       = __floats2half2_rn(p0, p1);
            *(__half2*)&PsW[(g + 8) * AT_S + nt * 8 + 2 * t] = __floats2half2_rn(p2, p3);
        }
        ps0 += __shfl_xor_sync(0xffffffffu, ps0, 1);
        ps0 += __shfl_xor_sync(0xffffffffu, ps0, 2);
        ps1 += __shfl_xor_sync(0xffffffffu, ps1, 1);
        ps1 += __shfl_xor_sync(0xffffffffu, ps1, 2);
        l0 = l0 * al0 + ps0;
        l1 = l1 * al1 + ps1;
        m0 = nm0; m1 = nm1;
#pragma unroll
        for (int nt = 0; nt < 8; nt++) {
            o[nt][0] *= al0; o[nt][1] *= al0;
            o[nt][2] *= al1; o[nt][3] *= al1;
        }
        __syncwarp();

        // O += P @ V ; V B-frags via ldmatrix.x4.trans on [key][d] tile
#pragma unroll
        for (int s = 0; s < 4; s++) {
            unsigned pa[4];
            const __half* pp = &PsW[g * AT_S + 16 * s + 2 * t];
            pa[0] = *(const unsigned*)(pp);
            pa[1] = *(const unsigned*)(pp + 8 * AT_S);
            pa[2] = *(const unsigned*)(pp + 8);
            pa[3] = *(const unsigned*)(pp + 8 * AT_S + 8);
#pragma unroll
            for (int nt2 = 0; nt2 < 4; nt2++) {
                uint32_t addr = vs_base +
                    ((16 * s + lm_row) * AT_S + nt2 * 16 + lm_col) * 2;
                unsigned r0, r1, r2, r3;
                ldsm4t(r0, r1, r2, r3, addr);
                unsigned b0[2] = {r0, r1}, b1[2] = {r2, r3};
                mma16(o[nt2 * 2 + 0], pa, b0);
                mma16(o[nt2 * 2 + 1], pa, b1);
            }
        }
        __syncthreads();
    }

    float i0 = 1.0f / l0, i1 = 1.0f / l1;
    int row0 = q0 + warp * 16 + g;
    __half* outb = ctx + (size_t)(b * 1024) * 768 + h * 64;
#pragma unroll
    for (int nt = 0; nt < 8; nt++) {
        int col = nt * 8 + 2 * t;
        *(__half2*)(outb + (size_t)row0 * 768 + col) =
            __floats2half2_rn(o[nt][0] * i0, o[nt][1] * i0);
        *(__half2*)(outb + (size_t)(row0 + 8) * 768 + col) =
            __floats2half2_rn(o[nt][2] * i1, o[nt][3] * i1);
    }
}

// ---------------------------------------------------------------------------
// Host launch (graph-capturable)
// ---------------------------------------------------------------------------
extern "C" void kernel_launch(void* const* d_in, const int* in_sizes, int n_in,
                              void* d_out, int out_size)
{
    const float* x      = (const float*)d_in[0];
    const float* ln1_g  = (const float*)d_in[1];
    const float* ln1_b  = (const float*)d_in[2];
    const float* qkv_w  = (const float*)d_in[3];
    const float* qkv_b  = (const float*)d_in[4];
    const float* proj_w = (const float*)d_in[5];
    const float* proj_b = (const float*)d_in[6];
    const float* ln2_g  = (const float*)d_in[7];
    const float* ln2_b  = (const float*)d_in[8];
    const float* fc1_w  = (const float*)d_in[9];
    const float* fc1_b  = (const float*)d_in[10];
    const float* fc2_w  = (const float*)d_in[11];
    const float* fc2_b  = (const float*)d_in[12];
    const float* ln3_g  = (const float*)d_in[13];
    const float* ln3_b  = (const float*)d_in[14];
    float* out = (float*)d_out;

    __half *xn1, *qkv, *ctx, *ffin, *hid, *wq, *wp, *w1, *w2;
    float *x2, *x3;
    cudaGetSymbolAddress((void**)&xn1,  g_xn1);
    cudaGetSymbolAddress((void**)&qkv,  g_qkv);
    cudaGetSymbolAddress((void**)&ctx,  g_ctx);
    cudaGetSymbolAddress((void**)&x2,   g_x2);
    cudaGetSymbolAddress((void**)&ffin, g_ffin);
    cudaGetSymbolAddress((void**)&hid,  g_hid);
    cudaGetSymbolAddress((void**)&x3,   g_x3);
    cudaGetSymbolAddress((void**)&wq,   g_wq);
    cudaGetSymbolAddress((void**)&wp,   g_wp);
    cudaGetSymbolAddress((void**)&w1,   g_w1);
    cudaGetSymbolAddress((void**)&w2,   g_w2);

    cudaFuncSetAttribute(gemm_f16<0,1,0>, cudaFuncAttributeMaxDynamicSharedMemorySize, GEMM_SMEM);
    cudaFuncSetAttribute(gemm_f16<1,1,0>, cudaFuncAttributeMaxDynamicSharedMemorySize, GEMM_SMEM);
    cudaFuncSetAttribute(gemm_f16<2,0,0>, cudaFuncAttributeMaxDynamicSharedMemorySize, GEMM_SMEM);
    cudaFuncSetAttribute(gemm_f16<2,0,1>, cudaFuncAttributeMaxDynamicSharedMemorySize, GEMM_SMEM);

    const int T = T_TOK;

    // weight transpose + fp16 round: W[K,N] -> Wt[N,K]
    transpose_half<<<dim3(2304 / 32, 768 / 32), 256>>>(qkv_w, wq, 768, 2304);
    transpose_half<<<dim3(768 / 32, 768 / 32), 256>>>(proj_w, wp, 768, 768);
    transpose_half<<<dim3(3072 / 32, 768 / 32), 256>>>(fc1_w, w1, 768, 3072);
    transpose_half<<<dim3(768 / 32, 3072 / 32), 256>>>(fc2_w, w2, 3072, 768);

    // 1) xn1 = LN1(x) [half]
    ln_kernel<1><<<T, 256>>>(x, ln1_g, ln1_b, xn1);
    // 2) qkv = xn1 @ qkv_w + qkv_b [half]
    gemm_f16<0,1,0><<<dim3(9, 128), 256, GEMM_SMEM>>>(xn1, wq, qkv_b, nullptr, qkv, T, 2304, 768);
    // 3) ctx = attention(qkv) [half]
    attn_f16<<<dim3(16, 192), 128>>>(qkv, ctx);
    // 4) x2 = x + ctx @ proj_w + proj_b [float]
    gemm_f16<2,0,0><<<dim3(3, 128), 256, GEMM_SMEM>>>(ctx, wp, proj_b, x, x2, T, 768, 768);
    // 5) ffin = LN2(x2) [half]
    ln_kernel<1><<<T, 256>>>(x2, ln2_g, ln2_b, ffin);
    // 6) hid = gelu(ffin @ fc1_w + fc1_b) [half]
    gemm_f16<1,1,0><<<dim3(12, 128), 256, GEMM_SMEM>>>(ffin, w1, fc1_b, nullptr, hid, T, 3072, 768);
    // 7) x3 = ffin + hid @ fc2_w + fc2_b [float] (residual from NORMALIZED tensor)
    gemm_f16<2,0,1><<<dim3(3, 128), 256, GEMM_SMEM>>>(hid, w2, fc2_b, ffin, x3, T, 768, 3072);
    // 8) out = LN3(x3)
    ln_kernel<0><<<T, 256>>>(x3, ln3_g, ln3_b, out);
}

// round 8
// speedup vs baseline: 8.3283x; 1.0277x over previous
#include <cuda_runtime.h>
#include <cuda_fp16.h>
#include <math.h>
#include <stdint.h>

// ---------------------------------------------------------------------------
// EncoderBlock: B=16, N=1024, DIM=768, HEADS=12, HEAD_DIM=64, HIDDEN=3072
// T = 16384 tokens. All matmuls: mma.sync m16n8k16 fp16 (fp32 accumulate).
// R6: 3-stage cp.async GEMM pipeline + frag double-buffer; attention Br=128.
// ---------------------------------------------------------------------------

#define T_TOK 16384

// Scratch (device globals: allocation-guard safe)
__device__ __half g_xn1 [T_TOK * 768];
__device__ __half g_qkv [T_TOK * 2304];
__device__ __half g_ctx [T_TOK * 768];
__device__ float  g_x2  [T_TOK * 768];
__device__ __half g_ffin[T_TOK * 768];
__device__ __half g_hid [T_TOK * 3072];
__device__ float  g_x3  [T_TOK * 768];
// transposed fp16 weights Wt[N,K]
__device__ __half g_wq  [2304 * 768];
__device__ __half g_wp  [768 * 768];
__device__ __half g_w1  [3072 * 768];
__device__ __half g_w2  [768 * 3072];

// ---------------------------------------------------------------------------
// helpers
// ---------------------------------------------------------------------------
__device__ __forceinline__ void mma16(float* c, const unsigned* a, const unsigned* b) {
    asm volatile(
        "mma.sync.aligned.m16n8k16.row.col.f32.f16.f16.f32 "
        "{%0,%1,%2,%3}, {%4,%5,%6,%7}, {%8,%9}, {%0,%1,%2,%3};\n"
        : "+f"(c[0]), "+f"(c[1]), "+f"(c[2]), "+f"(c[3])
        : "r"(a[0]), "r"(a[1]), "r"(a[2]), "r"(a[3]), "r"(b[0]), "r"(b[1]));
}

__device__ __forceinline__ void ldsm4t(unsigned& r0, unsigned& r1, unsigned& r2,
                                       unsigned& r3, uint32_t addr) {
    asm volatile("ldmatrix.sync.aligned.m8n8.x4.trans.shared.b16 {%0,%1,%2,%3}, [%4];"
                 : "=r"(r0), "=r"(r1), "=r"(r2), "=r"(r3) : "r"(addr));
}

__device__ __forceinline__ void cp16(__half* dst, const __half* src) {
    unsigned d = (unsigned)__cvta_generic_to_shared(dst);
    asm volatile("cp.async.cg.shared.global [%0], [%1], 16;\n" :: "r"(d), "l"(src));
}
__device__ __forceinline__ void cp_commit() { asm volatile("cp.async.commit_group;\n"); }
template <int N>
__device__ __forceinline__ void cp_wait() { asm volatile("cp.async.wait_group %0;\n" :: "n"(N)); }

// ---------------------------------------------------------------------------
// weight transpose + fp16 round: W[K,N] -> Wt[N,K] half
// ---------------------------------------------------------------------------
__global__ __launch_bounds__(256) void transpose_half(
    const float* __restrict__ in, __half* __restrict__ out, int K, int N)
{
    __shared__ float s[32][33];
    int n0 = blockIdx.x * 32, k0 = blockIdx.y * 32;
    int tx = threadIdx.x & 31, ty = threadIdx.x >> 5;
#pragma unroll
    for (int j = 0; j < 4; j++)
        s[ty + 8 * j][tx] = in[(size_t)(k0 + ty + 8 * j) * N + n0 + tx];
    __syncthreads();
#pragma unroll
    for (int j = 0; j < 4; j++)
        out[(size_t)(n0 + ty + 8 * j) * K + k0 + tx] = __float2half_rn(s[tx][ty + 8 * j]);
}

// ---------------------------------------------------------------------------
// LayerNorm over 768. OUTH: write half (GEMM A operand) else float.
// ---------------------------------------------------------------------------
template <int OUTH>
__global__ __launch_bounds__(256) void ln_kernel(
    const float* __restrict__ in, const float* __restrict__ g,
    const float* __restrict__ b, void* __restrict__ outv)
{
    int row = blockIdx.x;
    const float* p = in + (size_t)row * 768;
    float v[3];
    float s = 0.f, ss = 0.f;
#pragma unroll
    for (int i = 0; i < 3; i++) {
        v[i] = p[threadIdx.x + i * 256];
        s += v[i]; ss += v[i] * v[i];
    }
#pragma unroll
    for (int o = 16; o > 0; o >>= 1) {
        s  += __shfl_xor_sync(0xffffffffu, s,  o);
        ss += __shfl_xor_sync(0xffffffffu, ss, o);
    }
    __shared__ float rs[8], rss[8];
    int w = threadIdx.x >> 5, lane = threadIdx.x & 31;
    if (lane == 0) { rs[w] = s; rss[w] = ss; }
    __syncthreads();
    s = 0.f; ss = 0.f;
#pragma unroll
    for (int i = 0; i < 8; i++) { s += rs[i]; ss += rss[i]; }
    float mean = s * (1.0f / 768.0f);
    float var  = ss * (1.0f / 768.0f) - mean * mean;
    float rstd = rsqrtf(var + 1e-5f);
#pragma unroll
    for (int i = 0; i < 3; i++) {
        int c = threadIdx.x + i * 256;
        float r = (v[i] - mean) * rstd * g[c] + b[c];
        if (OUTH) ((__half*)outv)[(size_t)row * 768 + c] = __float2half_rn(r);
        else      ((float*)outv)[(size_t)row * 768 + c] = r;
    }
}

// ---------------------------------------------------------------------------
// fp16 mma GEMM v3: 3-stage cp.async pipeline + frag double buffering.
// C[M,N] = A[M,K] @ W[K,N] + bias; W transposed Wt[N,K].
//   EPI=0 none | EPI=1 exact GELU | EPI=2 += res
//   OUTH: out half else float. RESH: residual half else float.
// 128x256x32 CTA tile, 256 threads (8 warps 2x4), warp tile 64x64.
// ---------------------------------------------------------------------------
#define AS_S 40
#define BS_S 40
#define GA_BUF (128 * AS_S)
#define GB_BUF (256 * BS_S)
#define GEMM_SMEM (3 * (GA_BUF + GB_BUF) * 2)

template <int EPI, int OUTH, int RESH>
__global__ __launch_bounds__(256, 1) void gemm_f16(
    const __half* __restrict__ A, const __half* __restrict__ Bt,
    const float* __restrict__ bias, const void* __restrict__ resv,
    void* __restrict__ Cv, int M, int N, int K)
{
    extern __shared__ __half smh[];
    __half* As = smh;                      // [3][128][AS_S]
    __half* Bs = smh + 3 * GA_BUF;         // [3][256][BS_S]

    int tid = threadIdx.x;
    int warp = tid >> 5, lane = tid & 31;
    int g = lane >> 2, t = lane & 3;
    int wm = (warp & 1) * 64, wn = (warp >> 1) * 64;
    int bm = blockIdx.y * 128, bn = blockIdx.x * 256;

    float acc[4][8][4];
#pragma unroll
    for (int i = 0; i < 4; i++)
#pragma unroll
        for (int j = 0; j < 8; j++)
#pragma unroll
            for (int q = 0; q < 4; q++) acc[i][j][q] = 0.f;

    const __half* Agb = A + (size_t)bm * K;
    const __half* Bgb = Bt + (size_t)bn * K;

    int cr_a = tid >> 2, cc = (tid & 3) * 8;   // A/B copy maps (K-contiguous)
    int ntile = K >> 5;

    // prologue: tiles 0, 1 -> stages 0, 1
#pragma unroll
    for (int pt = 0; pt < 2; pt++) {
        __half* Ab = As + pt * GA_BUF;
        __half* Bb = Bs + pt * GB_BUF;
        int k0 = pt * 32;
#pragma unroll
        for (int i = 0; i < 2; i++) {
            int r = cr_a + i * 64;
            cp16(&Ab[r * AS_S + cc], Agb + (size_t)r * K + k0 + cc);
        }
#pragma unroll
        for (int i = 0; i < 4; i++) {
            int r = cr_a + i * 64;
            cp16(&Bb[r * BS_S + cc], Bgb + (size_t)r * K + k0 + cc);
        }
        cp_commit();
    }

    for (int tt = 0; tt < ntile; tt++) {
        // issue loads for tile tt+2 (stage (tt+2)%3 == (tt-1)%3, freed last iter)
        if (tt + 2 < ntile) {
            int st2 = (tt + 2) % 3;
            int k0 = (tt + 2) * 32;
            __half* Ab = As + st2 * GA_BUF;
            __half* Bb = Bs + st2 * GB_BUF;
#pragma unroll
            for (int i = 0; i < 2; i++) {
                int r = cr_a + i * 64;
                cp16(&Ab[r * AS_S + cc], Agb + (size_t)r * K + k0 + cc);
            }
#pragma unroll
            for (int i = 0; i < 4; i++) {
                int r = cr_a + i * 64;
                cp16(&Bb[r * BS_S + cc], Bgb + (size_t)r * K + k0 + cc);
            }
            cp_commit();
            cp_wait<2>();
        } else if (tt + 1 < ntile) {
            cp_wait<1>();
        } else {
            cp_wait<0>();
        }
        __syncthreads();

        int st = tt % 3;
        const __half* Abase = As + st * GA_BUF + (wm + g) * AS_S + 2 * t;
        const __half* Bbase = Bs + st * GB_BUF + (wn + g) * BS_S + 2 * t;

        // fragment double-buffer over the 2 k-steps
        unsigned a[2][4][4], b[2][8][2];
#pragma unroll
        for (int mt = 0; mt < 4; mt++) {
            const __half* p = Abase + mt * 16 * AS_S;
            a[0][mt][0] = *(const unsigned*)(p);
            a[0][mt][1] = *(const unsigned*)(p + 8 * AS_S);
            a[0][mt][2] = *(const unsigned*)(p + 8);
            a[0][mt][3] = *(const unsigned*)(p + 8 * AS_S + 8);
        }
#pragma unroll
        for (int nt = 0; nt < 8; nt++) {
            const __half* p = Bbase + nt * 8 * BS_S;
            b[0][nt][0] = *(const unsigned*)(p);
            b[0][nt][1] = *(const unsigned*)(p + 8);
        }
#pragma unroll
        for (int s = 0; s < 2; s++) {
            if (s == 0) {
                // prefetch k-step 1 fragments while k-step 0 mma issue
#pragma unroll
                for (int mt = 0; mt < 4; mt++) {
                    const __half* p = Abase + mt * 16 * AS_S + 16;
                    a[1][mt][0] = *(const unsigned*)(p);
                    a[1][mt][1] = *(const unsigned*)(p + 8 * AS_S);
                    a[1][mt][2] = *(const unsigned*)(p + 8);
                    a[1][mt][3] = *(const unsigned*)(p + 8 * AS_S + 8);
                }
#pragma unroll
                for (int nt = 0; nt < 8; nt++) {
                    const __half* p = Bbase + nt * 8 * BS_S + 16;
                    b[1][nt][0] = *(const unsigned*)(p);
                    b[1][nt][1] = *(const unsigned*)(p + 8);
                }
            }
#pragma unroll
            for (int mt = 0; mt < 4; mt++)
#pragma unroll
                for (int nt = 0; nt < 8; nt++)
                    mma16(acc[mt][nt], a[s][mt], b[s][nt]);
        }
        __syncthreads();
    }

    // epilogue
#pragma unroll
    for (int mt = 0; mt < 4; mt++) {
        int r0 = bm + wm + mt * 16 + g;
        int r1 = r0 + 8;
#pragma unroll
        for (int nt = 0; nt < 8; nt++) {
            int col = bn + wn + nt * 8 + 2 * t;
            float b0 = bias[col], b1 = bias[col + 1];
            float v0 = acc[mt][nt][0] + b0, v1 = acc[mt][nt][1] + b1;
            float v2 = acc[mt][nt][2] + b0, v3 = acc[mt][nt][3] + b1;
            if (EPI == 1) {
                v0 = 0.5f * v0 * (1.0f + erff(v0 * 0.70710678118654752f));
                v1 = 0.5f * v1 * (1.0f + erff(v1 * 0.70710678118654752f));
                v2 = 0.5f * v2 * (1.0f + erff(v2 * 0.70710678118654752f));
                v3 = 0.5f * v3 * (1.0f + erff(v3 * 0.70710678118654752f));
            }
            if (EPI == 2) {
                if (RESH) {
                    const __half* rh = (const __half*)resv;
                    float2 ra = __half22float2(*(const __half2*)(rh + (size_t)r0 * N + col));
                    float2 rb = __half22float2(*(const __half2*)(rh + (size_t)r1 * N + col));
                    v0 += ra.x; v1 += ra.y; v2 += rb.x; v3 += rb.y;
                } else {
                    const float* rf = (const float*)resv;
                    float2 ra = *(const float2*)(rf + (size_t)r0 * N + col);
                    float2 rb = *(const float2*)(rf + (size_t)r1 * N + col);
                    v0 += ra.x; v1 += ra.y; v2 += rb.x; v3 += rb.y;
                }
            }
            if (OUTH) {
                __half* Ch = (__half*)Cv;
                *(__half2*)(Ch + (size_t)r0 * N + col) = __floats2half2_rn(v0, v1);
                *(__half2*)(Ch + (size_t)r1 * N + col) = __floats2half2_rn(v2, v3);
            } else {
                float* Cf = (float*)Cv;
                *(float2*)(Cf + (size_t)r0 * N + col) = make_float2(v0, v1);
                *(float2*)(Cf + (size_t)r1 * N + col) = make_float2(v2, v3);
            }
        }
    }
}

// ---------------------------------------------------------------------------
// Flash attention fp16, Br=128, Bc=64, 256 threads (8 warps, 16 q-rows each).
// qkv half [T, 2304]: Q +0, K +768, V +1536 (head h: +h*64).
// ---------------------------------------------------------------------------
#define AT_S 72

__global__ __launch_bounds__(256) void attn_f16(
    const __half* __restrict__ qkv, __half* __restrict__ ctx)
{
    __shared__ __half sm[(128 + 64 + 64) * AT_S];
    __half* QPs = sm;                    // Q [128], later P strips
    __half* Ks  = sm + 128 * AT_S;
    __half* Vs  = sm + 192 * AT_S;
    uint32_t vs_base = (uint32_t)__cvta_generic_to_shared(Vs);

    int tid = threadIdx.x, warp = tid >> 5, lane = tid & 31;
    int g = lane >> 2, t = lane & 3;
    int bh = blockIdx.y, b = bh / 12, h = bh % 12;
    size_t base = (size_t)b * 1024 * 2304 + h * 64;
    int q0 = blockIdx.x * 128;

    // load Q [128 x 64] (scaled by 1/8)
    __half2 s2 = __floats2half2_rn(0.125f, 0.125f);
#pragma unroll
    for (int i = 0; i < 4; i++) {
        int idx = tid + i * 256;
        int r = idx >> 3, c = (idx & 7) * 8;
        uint4 u = *(const uint4*)(qkv + base + (size_t)(q0 + r) * 2304 + c);
        __half2* hp = (__half2*)&u;
        hp[0] = __hmul2(hp[0], s2); hp[1] = __hmul2(hp[1], s2);
        hp[2] = __hmul2(hp[2], s2); hp[3] = __hmul2(hp[3], s2);
        *(uint4*)&QPs[r * AT_S + c] = u;
    }
    __syncthreads();

    // Q fragments in regs for whole kernel (each warp: its 16-row strip)
    unsigned qa[4][4];
    {
        const __half* p0 = &QPs[(warp * 16 + g) * AT_S + 2 * t];
#pragma unroll
        for (int s = 0; s < 4; s++) {
            qa[s][0] = *(const unsigned*)(p0 + 16 * s);
            qa[s][1] = *(const unsigned*)(p0 + 16 * s + 8 * AT_S);
            qa[s][2] = *(const unsigned*)(p0 + 16 * s + 8);
            qa[s][3] = *(const unsigned*)(p0 + 16 * s + 8 * AT_S + 8);
        }
    }
    __syncthreads();   // QPs now free -> P buffer

    __half* PsW = QPs + warp * 16 * AT_S;

    float o[8][4];
#pragma unroll
    for (int i = 0; i < 8; i++)
#pragma unroll
        for (int j = 0; j < 4; j++) o[i][j] = 0.f;
    float m0 = -1e30f, m1 = -1e30f, l0 = 0.f, l1 = 0.f;

    int lm_row = ((lane >> 3) & 1) * 8 + (lane & 7);
    int lm_col = ((lane >> 4) & 1) * 8;

    for (int kt = 0; kt < 16; kt++) {
        // load K, V tiles [64 keys x 64 dims]
#pragma unroll
        for (int i = 0; i < 2; i++) {
            int idx = tid + i * 256;
            int r = idx >> 3, c = (idx & 7) * 8;
            const __half* kp = qkv + base + (size_t)(kt * 64 + r) * 2304 + 768 + c;
            *(uint4*)&Ks[r * AT_S + c] = *(const uint4*)kp;
            *(uint4*)&Vs[r * AT_S + c] = *(const uint4*)(kp + 768);
        }
        __syncthreads();

        // S = Q K^T (Q pre-scaled)
        float sc[8][4];
#pragma unroll
        for (int i = 0; i < 8; i++)
#pragma unroll
            for (int j = 0; j < 4; j++) sc[i][j] = 0.f;
#pragma unroll
        for (int s = 0; s < 4; s++) {
            unsigned bb[8][2];
#pragma unroll
            for (int nt = 0; nt < 8; nt++) {
                const __half* p = &Ks[(nt * 8 + g) * AT_S + 16 * s + 2 * t];
                bb[nt][0] = *(const unsigned*)(p);
                bb[nt][1] = *(const unsigned*)(p + 8);
            }
#pragma unroll
            for (int nt = 0; nt < 8; nt++)
                mma16(sc[nt], qa[s], bb[nt]);
        }

        // online softmax (rows g, g+8 of warp strip)
        float mx0 = -1e30f, mx1 = -1e30f;
#pragma unroll
        for (int nt = 0; nt < 8; nt++) {
            mx0 = fmaxf(mx0, fmaxf(sc[nt][0], sc[nt][1]));
            mx1 = fmaxf(mx1, fmaxf(sc[nt][2], sc[nt][3]));
        }
        mx0 = fmaxf(mx0, __shfl_xor_sync(0xffffffffu, mx0, 1));
        mx0 = fmaxf(mx0, __shfl_xor_sync(0xffffffffu, mx0, 2));
        mx1 = fmaxf(mx1, __shfl_xor_sync(0xffffffffu, mx1, 1));
        mx1 = fmaxf(mx1, __shfl_xor_sync(0xffffffffu, mx1, 2));
        float nm0 = fmaxf(m0, mx0), nm1 = fmaxf(m1, mx1);
        float al0 = __expf(m0 - nm0), al1 = __expf(m1 - nm1);
        float ps0 = 0.f, ps1 = 0.f;
#pragma unroll
        for (int nt = 0; nt < 8; nt++) {
            float p0 = __expf(sc[nt][0] - nm0);
            float p1 = __expf(sc[nt][1] - nm0);
            float p2 = __expf(sc[nt][2] - nm1);
            float p3 = __expf(sc[nt][3] - nm1);
            ps0 += p0 + p1; ps1 += p2 + p3;
            *(__half2*)&PsW[g * AT_S + nt * 8 + 2 * t]       = __floats2half2_rn(p0, p1);
            *(__half2*)&PsW[(g + 8) * AT_S + nt * 8 + 2 * t] = __floats2half2_rn(p2, p3);
        }
        ps0 += __shfl_xor_sync(0xffffffffu, ps0, 1);
        ps0 += __shfl_xor_sync(0xffffffffu, ps0, 2);
        ps1 += __shfl_xor_sync(0xffffffffu, ps1, 1);
        ps1 += __shfl_xor_sync(0xffffffffu, ps1, 2);
        l0 = l0 * al0 + ps0;
        l1 = l1 * al1 + ps1;
        m0 = nm0; m1 = nm1;
#pragma unroll
        for (int nt = 0; nt < 8; nt++) {
            o[nt][0] *= al0; o[nt][1] *= al0;
            o[nt][2] *= al1; o[nt][3] *= al1;
        }
        __syncwarp();

        // O += P @ V ; V B-frags via ldmatrix.x4.trans on [key][d] tile
#pragma unroll
        for (int s = 0; s < 4; s++) {
            unsigned pa[4];
            const __half* pp = &PsW[g * AT_S + 16 * s + 2 * t];
            pa[0] = *(const unsigned*)(pp);
            pa[1] = *(const unsigned*)(pp + 8 * AT_S);
            pa[2] = *(const unsigned*)(pp + 8);
            pa[3] = *(const unsigned*)(pp + 8 * AT_S + 8);
#pragma unroll
            for (int nt2 = 0; nt2 < 4; nt2++) {
                uint32_t addr = vs_base +
                    ((16 * s + lm_row) * AT_S + nt2 * 16 + lm_col) * 2;
                unsigned r0, r1, r2, r3;
                ldsm4t(r0, r1, r2, r3, addr);
                unsigned b0[2] = {r0, r1}, b1[2] = {r2, r3};
                mma16(o[nt2 * 2 + 0], pa, b0);
                mma16(o[nt2 * 2 + 1], pa, b1);
            }
        }
        __syncthreads();
    }

    float i0 = 1.0f / l0, i1 = 1.0f / l1;
    int row0 = q0 + warp * 16 + g;
    __half* outb = ctx + (size_t)(b * 1024) * 768 + h * 64;
#pragma unroll
    for (int nt = 0; nt < 8; nt++) {
        int col = nt * 8 + 2 * t;
        *(__half2*)(outb + (size_t)row0 * 768 + col) =
            __floats2half2_rn(o[nt][0] * i0, o[nt][1] * i0);
        *(__half2*)(outb + (size_t)(row0 + 8) * 768 + col) =
            __floats2half2_rn(o[nt][2] * i1, o[nt][3] * i1);
    }
}

// ---------------------------------------------------------------------------
// Host launch (graph-capturable)
// ---------------------------------------------------------------------------
extern "C" void kernel_launch(void* const* d_in, const int* in_sizes, int n_in,
                              void* d_out, int out_size)
{
    const float* x      = (const float*)d_in[0];
    const float* ln1_g  = (const float*)d_in[1];
    const float* ln1_b  = (const float*)d_in[2];
    const float* qkv_w  = (const float*)d_in[3];
    const float* qkv_b  = (const float*)d_in[4];
    const float* proj_w = (const float*)d_in[5];
    const float* proj_b = (const float*)d_in[6];
    const float* ln2_g  = (const float*)d_in[7];
    const float* ln2_b  = (const float*)d_in[8];
    const float* fc1_w  = (const float*)d_in[9];
    const float* fc1_b  = (const float*)d_in[10];
    const float* fc2_w  = (const float*)d_in[11];
    const float* fc2_b  = (const float*)d_in[12];
    const float* ln3_g  = (const float*)d_in[13];
    const float* ln3_b  = (const float*)d_in[14];
    float* out = (float*)d_out;

    __half *xn1, *qkv, *ctx, *ffin, *hid, *wq, *wp, *w1, *w2;
    float *x2, *x3;
    cudaGetSymbolAddress((void**)&xn1,  g_xn1);
    cudaGetSymbolAddress((void**)&qkv,  g_qkv);
    cudaGetSymbolAddress((void**)&ctx,  g_ctx);
    cudaGetSymbolAddress((void**)&x2,   g_x2);
    cudaGetSymbolAddress((void**)&ffin, g_ffin);
    cudaGetSymbolAddress((void**)&hid,  g_hid);
    cudaGetSymbolAddress((void**)&x3,   g_x3);
    cudaGetSymbolAddress((void**)&wq,   g_wq);
    cudaGetSymbolAddress((void**)&wp,   g_wp);
    cudaGetSymbolAddress((void**)&w1,   g_w1);
    cudaGetSymbolAddress((void**)&w2,   g_w2);

    cudaFuncSetAttribute(gemm_f16<0,1,0>, cudaFuncAttributeMaxDynamicSharedMemorySize, GEMM_SMEM);
    cudaFuncSetAttribute(gemm_f16<1,1,0>, cudaFuncAttributeMaxDynamicSharedMemorySize, GEMM_SMEM);
    cudaFuncSetAttribute(gemm_f16<2,0,0>, cudaFuncAttributeMaxDynamicSharedMemorySize, GEMM_SMEM);
    cudaFuncSetAttribute(gemm_f16<2,0,1>, cudaFuncAttributeMaxDynamicSharedMemorySize, GEMM_SMEM);

    const int T = T_TOK;

    // weight transpose + fp16 round: W[K,N] -> Wt[N,K]
    transpose_half<<<dim3(2304 / 32, 768 / 32), 256>>>(qkv_w, wq, 768, 2304);
    transpose_half<<<dim3(768 / 32, 768 / 32), 256>>>(proj_w, wp, 768, 768);
    transpose_half<<<dim3(3072 / 32, 768 / 32), 256>>>(fc1_w, w1, 768, 3072);
    transpose_half<<<dim3(768 / 32, 3072 / 32), 256>>>(fc2_w, w2, 3072, 768);

    // 1) xn1 = LN1(x) [half]
    ln_kernel<1><<<T, 256>>>(x, ln1_g, ln1_b, xn1);
    // 2) qkv = xn1 @ qkv_w + qkv_b [half]
    gemm_f16<0,1,0><<<dim3(9, 128), 256, GEMM_SMEM>>>(xn1, wq, qkv_b, nullptr, qkv, T, 2304, 768);
    // 3) ctx = attention(qkv) [half]
    attn_f16<<<dim3(8, 192), 256>>>(qkv, ctx);
    // 4) x2 = x + ctx @ proj_w + proj_b [float]
    gemm_f16<2,0,0><<<dim3(3, 128), 256, GEMM_SMEM>>>(ctx, wp, proj_b, x, x2, T, 768, 768);
    // 5) ffin = LN2(x2) [half]
    ln_kernel<1><<<T, 256>>>(x2, ln2_g, ln2_b, ffin);
    // 6) hid = gelu(ffin @ fc1_w + fc1_b) [half]
    gemm_f16<1,1,0><<<dim3(12, 128), 256, GEMM_SMEM>>>(ffin, w1, fc1_b, nullptr, hid, T, 3072, 768);
    // 7) x3 = ffin + hid @ fc2_w + fc2_b [float] (residual from NORMALIZED tensor)
    gemm_f16<2,0,1><<<dim3(3, 128), 256, GEMM_SMEM>>>(hid, w2, fc2_b, ffin, x3, T, 768, 3072);
    // 8) out = LN3(x3)
    ln_kernel<0><<<T, 256>>>(x3, ln3_g, ln3_b, out);
}